// round 1
// baseline (speedup 1.0000x reference)
#include <cuda_runtime.h>
#include <math.h>

#define Bk   8
#define Nk   1024
#define Dk   256
#define Hk   8
#define DHk  32
#define DFFk 1024
#define BN   (Bk*Nk)   // 8192

// ---------------- scratch (static device arrays; no allocation) ----------------
__device__ float g_Q [Bk*Hk*Nk*DHk];   // [b,h,n,d]  8 MB
__device__ float g_K [Bk*Hk*Nk*DHk];   // 8 MB
__device__ float g_V [Bk*Hk*Nk*DHk];   // 8 MB
__device__ float g_Y [BN*Dk];          // attn output, [b,n,h*32+d] 8 MB
__device__ float g_X1[BN*Dk];          // after AddNorm1  8 MB
__device__ float g_Hb[BN*DFFk];        // FFN hidden    32 MB
__device__ float g_RB[Bk*Nk*Nk];       // rel_bias      33.5 MB

// ---------------- kernel 1: fused QKV projection ----------------
// grid 512 (row tiles of 16), block 256.  col t -> (h = t>>5, d = t&31)
__global__ void qkv_kernel(const float* __restrict__ X,
                           const float* __restrict__ Wq, const float* __restrict__ bq,
                           const float* __restrict__ Wk, const float* __restrict__ bk,
                           const float* __restrict__ Wv, const float* __restrict__ bv) {
    __shared__ float Xs[16][256];
    const int rowbase = blockIdx.x * 16;
    const int t = threadIdx.x;

    const float4* Xg = (const float4*)(X + (size_t)rowbase * Dk);
    float4* Xs4 = (float4*)&Xs[0][0];
#pragma unroll
    for (int i = 0; i < 4; i++) Xs4[t + 256 * i] = Xg[t + 256 * i];
    __syncthreads();

    float aq[16], ak[16], av[16];
#pragma unroll
    for (int r = 0; r < 16; r++) { aq[r] = 0.f; ak[r] = 0.f; av[r] = 0.f; }

    for (int k = 0; k < 256; k++) {
        float wq = Wq[k * 256 + t];
        float wk = Wk[k * 256 + t];
        float wv = Wv[k * 256 + t];
#pragma unroll
        for (int r = 0; r < 16; r++) {
            float x = Xs[r][k];
            aq[r] += x * wq; ak[r] += x * wk; av[r] += x * wv;
        }
    }
    const int h = t >> 5, d = t & 31;
    const float bqv = bq[t], bkv = bk[t], bvv = bv[t];
#pragma unroll
    for (int r = 0; r < 16; r++) {
        int row = rowbase + r;
        int b = row >> 10, n = row & 1023;
        size_t idx = ((size_t)((b * Hk + h) * Nk + n)) * DHk + d;
        g_Q[idx] = aq[r] + bqv;
        g_K[idx] = ak[r] + bkv;
        g_V[idx] = av[r] + bvv;
    }
}

// ---------------- kernel 2: rel_bias = adj + attr + rep ----------------
__global__ void bias_kernel(const float4* __restrict__ a, const float4* __restrict__ b,
                            const float4* __restrict__ c) {
    int i = blockIdx.x * blockDim.x + threadIdx.x;   // grid exactly covers 2097152 quads
    float4 x = a[i], y = b[i], z = c[i];
    float4 o;
    o.x = x.x + y.x + z.x; o.y = x.y + y.y + z.y;
    o.z = x.z + y.z + z.z; o.w = x.w + y.w + z.w;
    ((float4*)g_RB)[i] = o;
}

// ---------------- kernel 3: fused attention ----------------
// grid (32 m-tiles, H, B), block 256 (8 warps x 32 lanes).
// SMEM: S[32][1024] scores, Qs[32][32], KV[128][33] (K/V chunk, padded).
#define ATTN_SMEM_FLOATS (32*1024 + 32*32 + 128*33)
__global__ void attn_kernel(const float* __restrict__ mask, float* __restrict__ attn_out) {
    extern __shared__ float sm[];
    float* S  = sm;
    float* Qs = sm + 32 * 1024;
    float* KV = Qs + 32 * 32;

    const int mtile = blockIdx.x, h = blockIdx.y, b = blockIdx.z;
    const int t = threadIdx.x, w = t >> 5, l = t & 31;
    const int m0 = mtile * 32;

    const float* Qg  = g_Q + ((size_t)((b * Hk + h) * Nk + m0)) * DHk;
    const float* Kg  = g_K + ((size_t)((b * Hk + h) * Nk)) * DHk;
    const float* Vg  = g_V + ((size_t)((b * Hk + h) * Nk)) * DHk;
    const float* RBg = g_RB + ((size_t)(b * Nk + m0)) * Nk;
    const float* mk  = mask + b * Nk;

    // load Q tile (1024 floats)
    ((float4*)Qs)[t] = ((const float4*)Qg)[t];

    const float scale = 0.17677669529663687f;  // 1/sqrt(32)

    // ---- S = Q K^T * scale + rel_bias, masked ----
    for (int c = 0; c < 8; c++) {
        __syncthreads();
        const float4* Ksrc = (const float4*)(Kg + (size_t)c * 128 * DHk);
#pragma unroll
        for (int i = 0; i < 4; i++) {
            int q = t + 256 * i;             // quad 0..1023
            int row = q >> 3, dq = q & 7;
            float4 v = Ksrc[q];
            float* dst = KV + row * 33 + dq * 4;
            dst[0] = v.x; dst[1] = v.y; dst[2] = v.z; dst[3] = v.w;
        }
        __syncthreads();

        float acc[4][4];
#pragma unroll
        for (int i = 0; i < 4; i++)
#pragma unroll
            for (int j = 0; j < 4; j++) acc[i][j] = 0.f;

#pragma unroll
        for (int d = 0; d < 32; d++) {
            float q0 = Qs[(w * 4 + 0) * 32 + d];
            float q1 = Qs[(w * 4 + 1) * 32 + d];
            float q2 = Qs[(w * 4 + 2) * 32 + d];
            float q3 = Qs[(w * 4 + 3) * 32 + d];
            float k0 = KV[(l      ) * 33 + d];
            float k1 = KV[(l + 32) * 33 + d];
            float k2 = KV[(l + 64) * 33 + d];
            float k3 = KV[(l + 96) * 33 + d];
            acc[0][0] += q0 * k0; acc[0][1] += q0 * k1; acc[0][2] += q0 * k2; acc[0][3] += q0 * k3;
            acc[1][0] += q1 * k0; acc[1][1] += q1 * k1; acc[1][2] += q1 * k2; acc[1][3] += q1 * k3;
            acc[2][0] += q2 * k0; acc[2][1] += q2 * k1; acc[2][2] += q2 * k2; acc[2][3] += q2 * k3;
            acc[3][0] += q3 * k0; acc[3][1] += q3 * k1; acc[3][2] += q3 * k2; acc[3][3] += q3 * k3;
        }

        float msk[4];
#pragma unroll
        for (int j = 0; j < 4; j++) msk[j] = mk[c * 128 + l + 32 * j];
#pragma unroll
        for (int i = 0; i < 4; i++) {
            int m = w * 4 + i;
#pragma unroll
            for (int j = 0; j < 4; j++) {
                int n = c * 128 + l + 32 * j;
                float s = acc[i][j] * scale + RBg[(size_t)m * Nk + n];
                S[m * 1024 + n] = (msk[j] > 0.f) ? s : -1e9f;
            }
        }
    }
    __syncthreads();

    // ---- softmax per row (warp w owns rows w*4 .. w*4+3), write attn ----
#pragma unroll
    for (int i = 0; i < 4; i++) {
        int m = w * 4 + i;
        float* Srow = S + m * 1024;
        float mx = -1e30f;
        for (int n = l; n < 1024; n += 32) mx = fmaxf(mx, Srow[n]);
#pragma unroll
        for (int o = 16; o > 0; o >>= 1) mx = fmaxf(mx, __shfl_xor_sync(0xffffffffu, mx, o));
        float sum = 0.f;
        for (int n = l; n < 1024; n += 32) {
            float e = __expf(Srow[n] - mx);
            Srow[n] = e; sum += e;
        }
#pragma unroll
        for (int o = 16; o > 0; o >>= 1) sum += __shfl_xor_sync(0xffffffffu, sum, o);
        float inv = 1.f / sum;
        float* Arow = attn_out + ((size_t)((b * Hk + h) * Nk + m0 + m)) * Nk;
        for (int n = l; n < 1024; n += 32) {
            float p = Srow[n] * inv;
            Srow[n] = p;
            Arow[n] = p;
        }
    }
    __syncthreads();

    // ---- Y = P @ V ----
    float ya[4] = {0.f, 0.f, 0.f, 0.f};
    for (int c = 0; c < 8; c++) {
        __syncthreads();
        const float4* Vsrc = (const float4*)(Vg + (size_t)c * 128 * DHk);
#pragma unroll
        for (int i = 0; i < 4; i++) {
            int q = t + 256 * i;
            int row = q >> 3, dq = q & 7;
            float4 v = Vsrc[q];
            float* dst = KV + row * 33 + dq * 4;
            dst[0] = v.x; dst[1] = v.y; dst[2] = v.z; dst[3] = v.w;
        }
        __syncthreads();
#pragma unroll 4
        for (int nn = 0; nn < 128; nn++) {
            float v = KV[nn * 33 + l];
            int n = c * 128 + nn;
            ya[0] += S[(w * 4 + 0) * 1024 + n] * v;
            ya[1] += S[(w * 4 + 1) * 1024 + n] * v;
            ya[2] += S[(w * 4 + 2) * 1024 + n] * v;
            ya[3] += S[(w * 4 + 3) * 1024 + n] * v;
        }
    }
#pragma unroll
    for (int i = 0; i < 4; i++) {
        int m = m0 + w * 4 + i;
        g_Y[((size_t)(b * Nk + m)) * Dk + h * DHk + l] = ya[i];
    }
}

// ---------------- kernel 4: O-proj + residual + LayerNorm1 ----------------
__global__ void oproj_ln_kernel(const float* __restrict__ X, const float* __restrict__ Wo,
                                const float* __restrict__ bo, const float* __restrict__ g1,
                                const float* __restrict__ b1) {
    __shared__ float Ys[16][256];
    __shared__ float res[16][256];
    const int rowbase = blockIdx.x * 16;
    const int t = threadIdx.x;

    const float4* Yg = (const float4*)(g_Y + (size_t)rowbase * Dk);
    float4* Ys4 = (float4*)&Ys[0][0];
#pragma unroll
    for (int i = 0; i < 4; i++) Ys4[t + 256 * i] = Yg[t + 256 * i];
    __syncthreads();

    float acc[16];
#pragma unroll
    for (int r = 0; r < 16; r++) acc[r] = 0.f;
    for (int k = 0; k < 256; k++) {
        float wv = Wo[k * 256 + t];
#pragma unroll
        for (int r = 0; r < 16; r++) acc[r] += Ys[r][k] * wv;
    }
    const float bias = bo[t];
#pragma unroll
    for (int r = 0; r < 16; r++)
        res[r][t] = X[(size_t)(rowbase + r) * Dk + t] + acc[r] + bias;
    __syncthreads();

    const int w = t >> 5, l = t & 31;
#pragma unroll
    for (int i = 0; i < 2; i++) {
        int r = w * 2 + i;
        float s = 0.f;
        for (int c = l; c < 256; c += 32) s += res[r][c];
#pragma unroll
        for (int o = 16; o > 0; o >>= 1) s += __shfl_xor_sync(0xffffffffu, s, o);
        float mu = s * (1.f / 256.f);
        float s2 = 0.f;
        for (int c = l; c < 256; c += 32) { float dv = res[r][c] - mu; s2 += dv * dv; }
#pragma unroll
        for (int o = 16; o > 0; o >>= 1) s2 += __shfl_xor_sync(0xffffffffu, s2, o);
        float rs = rsqrtf(s2 * (1.f / 256.f) + 1e-5f);
        for (int c = l; c < 256; c += 32)
            g_X1[(size_t)(rowbase + r) * Dk + c] = (res[r][c] - mu) * rs * g1[c] + b1[c];
    }
}

// ---------------- kernel 5: FFN layer 1 (X1 @ Wf1 + bf1, relu) ----------------
// grid (256 row tiles of 32, 2 col groups of 512), block 256, 2 cols/thread
__global__ void ffn1_kernel(const float* __restrict__ Wf1, const float* __restrict__ bf1) {
    __shared__ float Xs[32][256];
    const int rowbase = blockIdx.x * 32;
    const int t = threadIdx.x;
    const int c0 = blockIdx.y * 512 + t;  // second col = c0 + 256

    const float4* Xg = (const float4*)(g_X1 + (size_t)rowbase * Dk);
    float4* Xs4 = (float4*)&Xs[0][0];
#pragma unroll
    for (int i = 0; i < 8; i++) Xs4[t + 256 * i] = Xg[t + 256 * i];
    __syncthreads();

    float a0[32], a1[32];
#pragma unroll
    for (int r = 0; r < 32; r++) { a0[r] = 0.f; a1[r] = 0.f; }
    for (int k = 0; k < 256; k++) {
        float w0 = Wf1[k * DFFk + c0];
        float w1 = Wf1[k * DFFk + c0 + 256];
#pragma unroll
        for (int r = 0; r < 32; r++) {
            float x = Xs[r][k];
            a0[r] += x * w0; a1[r] += x * w1;
        }
    }
    const float bb0 = bf1[c0], bb1 = bf1[c0 + 256];
#pragma unroll
    for (int r = 0; r < 32; r++) {
        g_Hb[(size_t)(rowbase + r) * DFFk + c0]       = fmaxf(a0[r] + bb0, 0.f);
        g_Hb[(size_t)(rowbase + r) * DFFk + c0 + 256] = fmaxf(a1[r] + bb1, 0.f);
    }
}

// ---------------- kernel 6: FFN layer 2 + residual + LayerNorm2 -> d_out ----------------
#define FFN2_SMEM_BYTES ((16*1024 + 16*256) * 4)
__global__ void ffn2_ln_kernel(const float* __restrict__ Wf2, const float* __restrict__ bf2,
                               const float* __restrict__ g2, const float* __restrict__ b2,
                               float* __restrict__ out) {
    extern __shared__ float sm[];
    float (*Hs)[1024] = (float(*)[1024])sm;
    float (*res)[256] = (float(*)[256])(sm + 16 * 1024);
    const int rowbase = blockIdx.x * 16;
    const int t = threadIdx.x;

    const float4* Hg = (const float4*)(g_Hb + (size_t)rowbase * DFFk);
    float4* Hs4 = (float4*)sm;
#pragma unroll
    for (int i = 0; i < 16; i++) Hs4[t + 256 * i] = Hg[t + 256 * i];
    __syncthreads();

    float acc[16];
#pragma unroll
    for (int r = 0; r < 16; r++) acc[r] = 0.f;
    for (int k = 0; k < 1024; k++) {
        float wv = Wf2[k * Dk + t];
#pragma unroll
        for (int r = 0; r < 16; r++) acc[r] += Hs[r][k] * wv;
    }
    const float bias = bf2[t];
#pragma unroll
    for (int r = 0; r < 16; r++)
        res[r][t] = g_X1[(size_t)(rowbase + r) * Dk + t] + acc[r] + bias;
    __syncthreads();

    const int w = t >> 5, l = t & 31;
#pragma unroll
    for (int i = 0; i < 2; i++) {
        int r = w * 2 + i;
        float s = 0.f;
        for (int c = l; c < 256; c += 32) s += res[r][c];
#pragma unroll
        for (int o = 16; o > 0; o >>= 1) s += __shfl_xor_sync(0xffffffffu, s, o);
        float mu = s * (1.f / 256.f);
        float s2 = 0.f;
        for (int c = l; c < 256; c += 32) { float dv = res[r][c] - mu; s2 += dv * dv; }
#pragma unroll
        for (int o = 16; o > 0; o >>= 1) s2 += __shfl_xor_sync(0xffffffffu, s2, o);
        float rs = rsqrtf(s2 * (1.f / 256.f) + 1e-5f);
        for (int c = l; c < 256; c += 32)
            out[(size_t)(rowbase + r) * Dk + c] = (res[r][c] - mu) * rs * g2[c] + b2[c];
    }
}

// ---------------- launch ----------------
extern "C" void kernel_launch(void* const* d_in, const int* in_sizes, int n_in,
                              void* d_out, int out_size) {
    const float* X    = (const float*)d_in[0];
    const float* mask = (const float*)d_in[1];
    const float* adj  = (const float*)d_in[2];
    const float* attr = (const float*)d_in[3];
    const float* rep  = (const float*)d_in[4];
    const float* Wq = (const float*)d_in[5];  const float* bq = (const float*)d_in[6];
    const float* Wk = (const float*)d_in[7];  const float* bk = (const float*)d_in[8];
    const float* Wv = (const float*)d_in[9];  const float* bv = (const float*)d_in[10];
    const float* Wo = (const float*)d_in[11]; const float* bo = (const float*)d_in[12];
    const float* Wf1 = (const float*)d_in[13]; const float* bf1 = (const float*)d_in[14];
    const float* Wf2 = (const float*)d_in[15]; const float* bf2 = (const float*)d_in[16];
    const float* g1 = (const float*)d_in[17]; const float* b1 = (const float*)d_in[18];
    const float* g2 = (const float*)d_in[19]; const float* b2 = (const float*)d_in[20];

    float* out = (float*)d_out;
    float* attn_out = out + (size_t)BN * Dk;   // X2 first, then attn

    // opt-in smem (idempotent; host-side, not a stream op)
    cudaFuncSetAttribute(attn_kernel, cudaFuncAttributeMaxDynamicSharedMemorySize,
                         ATTN_SMEM_FLOATS * 4);
    cudaFuncSetAttribute(ffn2_ln_kernel, cudaFuncAttributeMaxDynamicSharedMemorySize,
                         FFN2_SMEM_BYTES);

    qkv_kernel<<<512, 256>>>(X, Wq, bq, Wk, bk, Wv, bv);
    bias_kernel<<<8192, 256>>>((const float4*)adj, (const float4*)attr, (const float4*)rep);
    attn_kernel<<<dim3(32, Hk, Bk), 256, ATTN_SMEM_FLOATS * 4>>>(mask, attn_out);
    oproj_ln_kernel<<<512, 256>>>(X, Wo, bo, g1, b1);
    ffn1_kernel<<<dim3(256, 2), 256>>>(Wf1, bf1);
    ffn2_ln_kernel<<<512, 256, FFN2_SMEM_BYTES>>>(Wf2, bf2, g2, b2, out);
}

// round 2
// speedup vs baseline: 2.0058x; 2.0058x over previous
#include <cuda_runtime.h>
#include <math.h>
#include <stdint.h>

#define Bk   8
#define Nk   1024
#define Dk   256
#define Hk   8
#define DHk  32
#define DFFk 1024
#define BN   (Bk*Nk)   // 8192

// ---------------- scratch ----------------
__device__ float g_Q [Bk*Hk*Nk*DHk];
__device__ float g_K [Bk*Hk*Nk*DHk];
__device__ float g_V [Bk*Hk*Nk*DHk];
__device__ float g_Y [BN*Dk];
__device__ float g_X1[BN*Dk];
__device__ float g_Hb[(size_t)BN*DFFk];

// ---------------- tf32 mma helpers ----------------
__device__ __forceinline__ float tfr(float x) {      // round-to-nearest tf32, as float bits
    unsigned u; asm("cvt.rna.tf32.f32 %0, %1;" : "=r"(u) : "f"(x));
    return __uint_as_float(u);
}
__device__ __forceinline__ unsigned FB(float x) { return __float_as_uint(x); }

__device__ __forceinline__ void mma8(float* d, const unsigned* a, unsigned b0, unsigned b1) {
    asm volatile("mma.sync.aligned.m16n8k8.row.col.f32.tf32.tf32.f32 "
        "{%0,%1,%2,%3},{%4,%5,%6,%7},{%8,%9},{%0,%1,%2,%3};"
        : "+f"(d[0]), "+f"(d[1]), "+f"(d[2]), "+f"(d[3])
        : "r"(a[0]), "r"(a[1]), "r"(a[2]), "r"(a[3]), "r"(b0), "r"(b1));
}

// =====================================================================
// Generic 128x64 tile GEMM, C = A[M,K] @ B[K,NTOT] tile, tf32 mma.
// MODE 0: Out[row*NTOT+col] = relu(acc + bias[col])          (ffn1)
// MODE 1: scatter rounded (acc + bias[col]) to [b,h,n,d]     (qkv)
// block 256 = 8 warps (4 m-rows x 2 n-cols), warp tile 32x32.
// =====================================================================
template<int MODE>
__global__ void gemm_plain(const float* __restrict__ A, const float* __restrict__ Bw,
                           const float* __restrict__ bias, float* __restrict__ Out,
                           int K, int NTOT) {
    __shared__ float As[128][36];
    __shared__ float Bs[32][72];
    const int t = threadIdx.x, l = t & 31, wid = t >> 5;
    const int wm = wid & 3, wn = wid >> 2;
    const int mbase = blockIdx.x * 128, nbase = blockIdx.y * 64;

    float acc[2][4][4];
#pragma unroll
    for (int mt = 0; mt < 2; mt++)
#pragma unroll
        for (int nt = 0; nt < 4; nt++)
#pragma unroll
            for (int i = 0; i < 4; i++) acc[mt][nt][i] = 0.f;

    for (int kc = 0; kc < K; kc += 32) {
#pragma unroll
        for (int i = 0; i < 4; i++) {
            int idx = t + i * 256;
            int r = idx >> 3, q = idx & 7;
            float4 v = *(const float4*)(A + (size_t)(mbase + r) * K + kc + q * 4);
            float* d = &As[r][q * 4];
            d[0] = tfr(v.x); d[1] = tfr(v.y); d[2] = tfr(v.z); d[3] = tfr(v.w);
        }
#pragma unroll
        for (int i = 0; i < 2; i++) {
            int idx = t + i * 256;
            int k = idx >> 4, q = idx & 15;
            float4 v = *(const float4*)(Bw + (size_t)(kc + k) * NTOT + nbase + q * 4);
            float* d = &Bs[k][q * 4];
            d[0] = tfr(v.x); d[1] = tfr(v.y); d[2] = tfr(v.z); d[3] = tfr(v.w);
        }
        __syncthreads();
#pragma unroll
        for (int ks = 0; ks < 4; ks++) {
            unsigned a[2][4];
#pragma unroll
            for (int mt = 0; mt < 2; mt++) {
                const float* p = &As[wm * 32 + mt * 16 + (l >> 2)][ks * 8 + (l & 3)];
                a[mt][0] = FB(p[0]); a[mt][1] = FB(p[8 * 36]);
                a[mt][2] = FB(p[4]); a[mt][3] = FB(p[8 * 36 + 4]);
            }
#pragma unroll
            for (int nt = 0; nt < 4; nt++) {
                const float* p = &Bs[ks * 8 + (l & 3)][wn * 32 + nt * 8 + (l >> 2)];
                unsigned b0 = FB(p[0]), b1 = FB(p[4 * 72]);
                mma8(acc[0][nt], a[0], b0, b1);
                mma8(acc[1][nt], a[1], b0, b1);
            }
        }
        __syncthreads();
    }

#pragma unroll
    for (int mt = 0; mt < 2; mt++)
#pragma unroll
        for (int nt = 0; nt < 4; nt++) {
            int gcol = nbase + wn * 32 + nt * 8 + (l & 3) * 2;
            float bb0 = bias[gcol], bb1 = bias[gcol + 1];
#pragma unroll
            for (int half = 0; half < 2; half++) {
                int grow = mbase + wm * 32 + mt * 16 + (l >> 2) + half * 8;
                float v0 = acc[mt][nt][half * 2 + 0] + bb0;
                float v1 = acc[mt][nt][half * 2 + 1] + bb1;
                if (MODE == 0) {
                    *(float2*)(Out + (size_t)grow * NTOT + gcol) =
                        make_float2(fmaxf(v0, 0.f), fmaxf(v1, 0.f));
                } else {
                    int h = gcol >> 5, dd = gcol & 31;
                    int bb = grow >> 10, nn = grow & 1023;
                    float* p = Out + ((size_t)((bb * Hk + h) * Nk + nn)) * DHk + dd;
                    *(float2*)p = make_float2(tfr(v0), tfr(v1));
                }
            }
        }
}

// =====================================================================
// 64-row GEMM with full-row (N=256) output + residual + LayerNorm.
// block 256 = 8 warps (2 m x 4 n), warp tile 32x64.  Out = LN(A@B + bias + R)
// =====================================================================
#define LN_SMEM_BYTES (64 * 258 * 4)   // res overlays As+Bs
__global__ void gemm_ln(const float* __restrict__ A, const float* __restrict__ Bw,
                        const float* __restrict__ bias, const float* __restrict__ R,
                        const float* __restrict__ gam, const float* __restrict__ bet,
                        float* __restrict__ Out, int K) {
    extern __shared__ float sm[];
    float* As = sm;             // [64][36]  = 2304 floats
    float* Bs = sm + 2304;      // [32][264] = 8448 floats
    const int t = threadIdx.x, l = t & 31, wid = t >> 5;
    const int wm = wid & 1, wn = wid >> 1;
    const int mbase = blockIdx.x * 64;

    float acc[2][8][4];
#pragma unroll
    for (int mt = 0; mt < 2; mt++)
#pragma unroll
        for (int nt = 0; nt < 8; nt++)
#pragma unroll
            for (int i = 0; i < 4; i++) acc[mt][nt][i] = 0.f;

    for (int kc = 0; kc < K; kc += 32) {
#pragma unroll
        for (int i = 0; i < 2; i++) {
            int idx = t + i * 256;
            int r = idx >> 3, q = idx & 7;
            float4 v = *(const float4*)(A + (size_t)(mbase + r) * K + kc + q * 4);
            float* d = &As[r * 36 + q * 4];
            d[0] = tfr(v.x); d[1] = tfr(v.y); d[2] = tfr(v.z); d[3] = tfr(v.w);
        }
#pragma unroll
        for (int i = 0; i < 8; i++) {
            int idx = t + i * 256;
            int k = idx >> 6, q = idx & 63;
            float4 v = *(const float4*)(Bw + (size_t)(kc + k) * 256 + q * 4);
            float* d = &Bs[k * 264 + q * 4];
            d[0] = tfr(v.x); d[1] = tfr(v.y); d[2] = tfr(v.z); d[3] = tfr(v.w);
        }
        __syncthreads();
#pragma unroll
        for (int ks = 0; ks < 4; ks++) {
            unsigned a[2][4];
#pragma unroll
            for (int mt = 0; mt < 2; mt++) {
                const float* p = &As[(wm * 32 + mt * 16 + (l >> 2)) * 36 + ks * 8 + (l & 3)];
                a[mt][0] = FB(p[0]); a[mt][1] = FB(p[8 * 36]);
                a[mt][2] = FB(p[4]); a[mt][3] = FB(p[8 * 36 + 4]);
            }
#pragma unroll
            for (int nt = 0; nt < 8; nt++) {
                const float* p = &Bs[(ks * 8 + (l & 3)) * 264 + wn * 64 + nt * 8 + (l >> 2)];
                unsigned b0 = FB(p[0]), b1 = FB(p[4 * 264]);
                mma8(acc[0][nt], a[0], b0, b1);
                mma8(acc[1][nt], a[1], b0, b1);
            }
        }
        __syncthreads();
    }

    // ---- epilogue: dump accumulators to res (overlays As/Bs), residual + LN ----
    float* res = sm;  // stride 258
#pragma unroll
    for (int mt = 0; mt < 2; mt++)
#pragma unroll
        for (int nt = 0; nt < 8; nt++) {
            int m = wm * 32 + mt * 16 + (l >> 2);
            int n = wn * 64 + nt * 8 + (l & 3) * 2;
            *(float2*)&res[m * 258 + n] = make_float2(acc[mt][nt][0], acc[mt][nt][1]);
            *(float2*)&res[(m + 8) * 258 + n] = make_float2(acc[mt][nt][2], acc[mt][nt][3]);
        }
    __syncthreads();

#pragma unroll
    for (int i = 0; i < 8; i++) {
        int r = wid * 8 + i;
        int grow = mbase + r;
        float s = 0.f;
        for (int c = l; c < 256; c += 32) {
            float v = res[r * 258 + c] + R[(size_t)grow * 256 + c] + bias[c];
            res[r * 258 + c] = v;
            s += v;
        }
#pragma unroll
        for (int o = 16; o > 0; o >>= 1) s += __shfl_xor_sync(0xffffffffu, s, o);
        float mu = s * (1.f / 256.f);
        float s2 = 0.f;
        for (int c = l; c < 256; c += 32) { float dv = res[r * 258 + c] - mu; s2 += dv * dv; }
#pragma unroll
        for (int o = 16; o > 0; o >>= 1) s2 += __shfl_xor_sync(0xffffffffu, s2, o);
        float rs = rsqrtf(s2 * (1.f / 256.f) + 1e-5f);
        for (int c = l; c < 256; c += 32)
            Out[(size_t)grow * 256 + c] = (res[r * 258 + c] - mu) * rs * gam[c] + bet[c];
    }
}

// =====================================================================
// Fused attention: S = QK^T*scale + (adj+attr+rep), mask, softmax,
// write attn, Y = P@V.   32 queries/block, 8 warps (2 m x 4 n), tf32 mma.
// =====================================================================
#define SP 1028
#define ATTN_SMEM_BYTES ((32*SP + 32*36 + 128*36) * 4)
__global__ void attn_kernel(const float* __restrict__ mask, const float* __restrict__ adj,
                            const float* __restrict__ attr, const float* __restrict__ rep,
                            float* __restrict__ attn_out) {
    extern __shared__ float sm[];
    float* S  = sm;                 // [32][SP]
    float* Qs = sm + 32 * SP;       // [32][36]
    float* KV = Qs + 32 * 36;       // [128][36]

    const int t = threadIdx.x, l = t & 31, wid = t >> 5;
    const int wm = wid & 1, wn = wid >> 1;
    const int m0 = blockIdx.x * 32, h = blockIdx.y, b = blockIdx.z;

    const float* Qg = g_Q + ((size_t)((b * Hk + h) * Nk + m0)) * DHk;
    const float* Kg = g_K + ((size_t)((b * Hk + h) * Nk)) * DHk;
    const float* Vg = g_V + ((size_t)((b * Hk + h) * Nk)) * DHk;
    const float* mkp = mask + b * Nk;
    const float scale = 0.17677669529663687f;

    {   // load Q tile (already tf32-rounded by qkv kernel)
        int r = t >> 3, q = t & 7;
        float4 v = ((const float4*)Qg)[t];
        float* d = &Qs[r * 36 + q * 4];
        d[0] = v.x; d[1] = v.y; d[2] = v.z; d[3] = v.w;
    }
    __syncthreads();

    unsigned aq[4][4];
#pragma unroll
    for (int kt = 0; kt < 4; kt++) {
        const float* p = &Qs[(wm * 16 + (l >> 2)) * 36 + kt * 8 + (l & 3)];
        aq[kt][0] = FB(p[0]); aq[kt][1] = FB(p[8 * 36]);
        aq[kt][2] = FB(p[4]); aq[kt][3] = FB(p[8 * 36 + 4]);
    }

    // ---- scores ----
    for (int c = 0; c < 8; c++) {
        __syncthreads();
#pragma unroll
        for (int i = 0; i < 4; i++) {
            int idx = t + i * 256;
            int r = idx >> 3, q = idx & 7;
            float4 v = ((const float4*)(Kg + (size_t)c * 128 * DHk))[idx];
            float* d = &KV[r * 36 + q * 4];
            d[0] = v.x; d[1] = v.y; d[2] = v.z; d[3] = v.w;
        }
        __syncthreads();

        float acc[4][4];
#pragma unroll
        for (int nt = 0; nt < 4; nt++)
#pragma unroll
            for (int i = 0; i < 4; i++) acc[nt][i] = 0.f;
#pragma unroll
        for (int kt = 0; kt < 4; kt++)
#pragma unroll
            for (int nt = 0; nt < 4; nt++) {
                const float* p = &KV[(wn * 32 + nt * 8 + (l >> 2)) * 36 + kt * 8 + (l & 3)];
                unsigned b0 = FB(p[0]), b1 = FB(p[4]);
                mma8(acc[nt], aq[kt], b0, b1);
            }

#pragma unroll
        for (int nt = 0; nt < 4; nt++) {
            int n = c * 128 + wn * 32 + nt * 8 + (l & 3) * 2;
            float2 mk2 = *(const float2*)(mkp + n);
#pragma unroll
            for (int half = 0; half < 2; half++) {
                int m = wm * 16 + (l >> 2) + half * 8;
                size_t ri = ((size_t)(b * Nk + m0 + m)) * Nk + n;
                float2 a1 = *(const float2*)(adj + ri);
                float2 a2 = *(const float2*)(attr + ri);
                float2 a3 = *(const float2*)(rep + ri);
                float s0 = acc[nt][half * 2 + 0] * scale + a1.x + a2.x + a3.x;
                float s1 = acc[nt][half * 2 + 1] * scale + a1.y + a2.y + a3.y;
                if (!(mk2.x > 0.f)) s0 = -1e9f;
                if (!(mk2.y > 0.f)) s1 = -1e9f;
                *(float2*)&S[m * SP + n] = make_float2(s0, s1);
            }
        }
    }
    __syncthreads();

    // ---- softmax (warp wid owns rows wid*4..wid*4+3); write attn; round P ----
#pragma unroll
    for (int i = 0; i < 4; i++) {
        int m = wid * 4 + i;
        float* row = S + m * SP;
        float mx = -1e30f;
        for (int n = l; n < 1024; n += 32) mx = fmaxf(mx, row[n]);
#pragma unroll
        for (int o = 16; o > 0; o >>= 1) mx = fmaxf(mx, __shfl_xor_sync(0xffffffffu, mx, o));
        float sum = 0.f;
        for (int n = l; n < 1024; n += 32) {
            float e = __expf(row[n] - mx);
            row[n] = e; sum += e;
        }
#pragma unroll
        for (int o = 16; o > 0; o >>= 1) sum += __shfl_xor_sync(0xffffffffu, sum, o);
        float inv = 1.f / sum;
        float* Arow = attn_out + ((size_t)((b * Hk + h) * Nk + m0 + m)) * Nk;
        for (int n = l; n < 1024; n += 32) {
            float p = row[n] * inv;
            Arow[n] = p;
            row[n] = tfr(p);
        }
    }

    // ---- Y = P @ V  (two independent accumulation chains) ----
    float av0[4] = {0.f, 0.f, 0.f, 0.f};
    float av1[4] = {0.f, 0.f, 0.f, 0.f};
    for (int c = 0; c < 8; c++) {
        __syncthreads();
#pragma unroll
        for (int i = 0; i < 4; i++) {
            int idx = t + i * 256;
            int r = idx >> 3, q = idx & 7;
            float4 v = ((const float4*)(Vg + (size_t)c * 128 * DHk))[idx];
            float* d = &KV[r * 36 + q * 4];
            d[0] = v.x; d[1] = v.y; d[2] = v.z; d[3] = v.w;
        }
        __syncthreads();
#pragma unroll
        for (int ks = 0; ks < 16; ks++) {
            const float* pa = &S[(wm * 16 + (l >> 2)) * SP + c * 128 + ks * 8 + (l & 3)];
            unsigned a[4];
            a[0] = FB(pa[0]); a[1] = FB(pa[8 * SP]);
            a[2] = FB(pa[4]); a[3] = FB(pa[8 * SP + 4]);
            const float* pb = &KV[(ks * 8 + (l & 3)) * 36 + wn * 8 + (l >> 2)];
            unsigned b0 = FB(pb[0]), b1 = FB(pb[4 * 36]);
            mma8((ks & 1) ? av1 : av0, a, b0, b1);
        }
    }
    {
        int m = m0 + wm * 16 + (l >> 2);
        int d = wn * 8 + (l & 3) * 2;
        float* yp = g_Y + ((size_t)(b * Nk + m)) * Dk + h * DHk + d;
        *(float2*)yp = make_float2(av0[0] + av1[0], av0[1] + av1[1]);
        *(float2*)(yp + 8 * Dk) = make_float2(av0[2] + av1[2], av0[3] + av1[3]);
    }
}

// ---------------- launch ----------------
extern "C" void kernel_launch(void* const* d_in, const int* in_sizes, int n_in,
                              void* d_out, int out_size) {
    const float* X    = (const float*)d_in[0];
    const float* mask = (const float*)d_in[1];
    const float* adj  = (const float*)d_in[2];
    const float* attr = (const float*)d_in[3];
    const float* rep  = (const float*)d_in[4];
    const float* Wq = (const float*)d_in[5];  const float* bq = (const float*)d_in[6];
    const float* Wk = (const float*)d_in[7];  const float* bk = (const float*)d_in[8];
    const float* Wv = (const float*)d_in[9];  const float* bv = (const float*)d_in[10];
    const float* Wo = (const float*)d_in[11]; const float* bo = (const float*)d_in[12];
    const float* Wf1 = (const float*)d_in[13]; const float* bf1 = (const float*)d_in[14];
    const float* Wf2 = (const float*)d_in[15]; const float* bf2 = (const float*)d_in[16];
    const float* g1 = (const float*)d_in[17]; const float* b1 = (const float*)d_in[18];
    const float* g2 = (const float*)d_in[19]; const float* b2 = (const float*)d_in[20];

    float* out = (float*)d_out;
    float* attn_out = out + (size_t)BN * Dk;

    cudaFuncSetAttribute(attn_kernel, cudaFuncAttributeMaxDynamicSharedMemorySize,
                         ATTN_SMEM_BYTES);
    cudaFuncSetAttribute(gemm_ln, cudaFuncAttributeMaxDynamicSharedMemorySize,
                         LN_SMEM_BYTES);

    // QKV projections (tf32-rounded outputs, head-scattered)
    float* gq; cudaGetSymbolAddress((void**)&gq, g_Q);
    float* gk; cudaGetSymbolAddress((void**)&gk, g_K);
    float* gv; cudaGetSymbolAddress((void**)&gv, g_V);
    float* gy; cudaGetSymbolAddress((void**)&gy, g_Y);
    float* gx1; cudaGetSymbolAddress((void**)&gx1, g_X1);
    float* ghb; cudaGetSymbolAddress((void**)&ghb, g_Hb);

    gemm_plain<1><<<dim3(64, 4), 256>>>(X, Wq, bq, gq, 256, 256);
    gemm_plain<1><<<dim3(64, 4), 256>>>(X, Wk, bk, gk, 256, 256);
    gemm_plain<1><<<dim3(64, 4), 256>>>(X, Wv, bv, gv, 256, 256);

    attn_kernel<<<dim3(32, Hk, Bk), 256, ATTN_SMEM_BYTES>>>(mask, adj, attr, rep, attn_out);

    gemm_ln<<<128, 256, LN_SMEM_BYTES>>>(gy, Wo, bo, X, g1, b1, gx1, 256);
    gemm_plain<0><<<dim3(64, 16), 256>>>(gx1, Wf1, bf1, ghb, 256, 1024);
    gemm_ln<<<128, 256, LN_SMEM_BYTES>>>(ghb, Wf2, bf2, gx1, g2, b2, out, 1024);
}

// round 4
// speedup vs baseline: 2.4765x; 1.2347x over previous
#include <cuda_runtime.h>
#include <math.h>
#include <stdint.h>

#define Bk   8
#define Nk   1024
#define Dk   256
#define Hk   8
#define DHk  32
#define DFFk 1024
#define BN   (Bk*Nk)   // 8192

// ---------------- scratch ----------------
__device__ float g_Q [Bk*Hk*Nk*DHk];
__device__ float g_K [Bk*Hk*Nk*DHk];
__device__ float g_V [Bk*Hk*Nk*DHk];
__device__ float g_Y [BN*Dk];
__device__ float g_X1[BN*Dk];
__device__ float g_Hb[(size_t)BN*DFFk];
__device__ float g_RB[(size_t)Bk*Nk*Nk];

// ---------------- helpers ----------------
__device__ __forceinline__ float tfr(float x) {
    unsigned u; asm("cvt.rna.tf32.f32 %0, %1;" : "=r"(u) : "f"(x));
    return __uint_as_float(u);
}
__device__ __forceinline__ unsigned FB(float x) { return __float_as_uint(x); }

__device__ __forceinline__ void mma8(float* d, const unsigned* a, unsigned b0, unsigned b1) {
    asm volatile("mma.sync.aligned.m16n8k8.row.col.f32.tf32.tf32.f32 "
        "{%0,%1,%2,%3},{%4,%5,%6,%7},{%8,%9},{%0,%1,%2,%3};"
        : "+f"(d[0]), "+f"(d[1]), "+f"(d[2]), "+f"(d[3])
        : "r"(a[0]), "r"(a[1]), "r"(a[2]), "r"(a[3]), "r"(b0), "r"(b1));
}

__device__ __forceinline__ void cpa16(void* s, const void* g) {
    uint32_t sa = (uint32_t)__cvta_generic_to_shared(s);
    asm volatile("cp.async.cg.shared.global [%0], [%1], 16;" :: "r"(sa), "l"(g));
}
__device__ __forceinline__ void cpa_commit() { asm volatile("cp.async.commit_group;"); }
template<int N> __device__ __forceinline__ void cpa_wait() {
    asm volatile("cp.async.wait_group %0;" :: "n"(N));
}

// load a 128x32 float chunk into smem with pad-36 rows
__device__ __forceinline__ void load_chunk(float* buf, const float* src, int t) {
#pragma unroll
    for (int i = 0; i < 4; i++) {
        int q = t + i * 256;
        int row = q >> 3, c4 = q & 7;
        cpa16(buf + row * 36 + c4 * 4, src + q * 4);
    }
}

// ---------------- kernel: rel_bias = adj + attr + rep ----------------
__global__ void bias_kernel(const float4* __restrict__ a, const float4* __restrict__ b,
                            const float4* __restrict__ c) {
    int i = blockIdx.x * blockDim.x + threadIdx.x;
    float4 x = a[i], y = b[i], z = c[i];
    float4 o;
    o.x = x.x + y.x + z.x; o.y = x.y + y.y + z.y;
    o.z = x.z + y.z + z.z; o.w = x.w + y.w + z.w;
    ((float4*)g_RB)[i] = o;
}

// =====================================================================
// gemm_plain / gemm_ln
// =====================================================================
template<int MODE>
__global__ void gemm_plain(const float* __restrict__ A, const float* __restrict__ Bw,
                           const float* __restrict__ bias, float* __restrict__ Out,
                           int K, int NTOT) {
    __shared__ float As[128][36];
    __shared__ float Bs[32][72];
    const int t = threadIdx.x, l = t & 31, wid = t >> 5;
    const int wm = wid & 3, wn = wid >> 2;
    const int mbase = blockIdx.x * 128, nbase = blockIdx.y * 64;

    float acc[2][4][4];
#pragma unroll
    for (int mt = 0; mt < 2; mt++)
#pragma unroll
        for (int nt = 0; nt < 4; nt++)
#pragma unroll
            for (int i = 0; i < 4; i++) acc[mt][nt][i] = 0.f;

    for (int kc = 0; kc < K; kc += 32) {
#pragma unroll
        for (int i = 0; i < 4; i++) {
            int idx = t + i * 256;
            int r = idx >> 3, q = idx & 7;
            float4 v = *(const float4*)(A + (size_t)(mbase + r) * K + kc + q * 4);
            float* d = &As[r][q * 4];
            d[0] = tfr(v.x); d[1] = tfr(v.y); d[2] = tfr(v.z); d[3] = tfr(v.w);
        }
#pragma unroll
        for (int i = 0; i < 2; i++) {
            int idx = t + i * 256;
            int k = idx >> 4, q = idx & 15;
            float4 v = *(const float4*)(Bw + (size_t)(kc + k) * NTOT + nbase + q * 4);
            float* d = &Bs[k][q * 4];
            d[0] = tfr(v.x); d[1] = tfr(v.y); d[2] = tfr(v.z); d[3] = tfr(v.w);
        }
        __syncthreads();
#pragma unroll
        for (int ks = 0; ks < 4; ks++) {
            unsigned a[2][4];
#pragma unroll
            for (int mt = 0; mt < 2; mt++) {
                const float* p = &As[wm * 32 + mt * 16 + (l >> 2)][ks * 8 + (l & 3)];
                a[mt][0] = FB(p[0]); a[mt][1] = FB(p[8 * 36]);
                a[mt][2] = FB(p[4]); a[mt][3] = FB(p[8 * 36 + 4]);
            }
#pragma unroll
            for (int nt = 0; nt < 4; nt++) {
                const float* p = &Bs[ks * 8 + (l & 3)][wn * 32 + nt * 8 + (l >> 2)];
                unsigned b0 = FB(p[0]), b1 = FB(p[4 * 72]);
                mma8(acc[0][nt], a[0], b0, b1);
                mma8(acc[1][nt], a[1], b0, b1);
            }
        }
        __syncthreads();
    }

#pragma unroll
    for (int mt = 0; mt < 2; mt++)
#pragma unroll
        for (int nt = 0; nt < 4; nt++) {
            int gcol = nbase + wn * 32 + nt * 8 + (l & 3) * 2;
            float bb0 = bias[gcol], bb1 = bias[gcol + 1];
#pragma unroll
            for (int half = 0; half < 2; half++) {
                int grow = mbase + wm * 32 + mt * 16 + (l >> 2) + half * 8;
                float v0 = acc[mt][nt][half * 2 + 0] + bb0;
                float v1 = acc[mt][nt][half * 2 + 1] + bb1;
                if (MODE == 0) {
                    *(float2*)(Out + (size_t)grow * NTOT + gcol) =
                        make_float2(fmaxf(v0, 0.f), fmaxf(v1, 0.f));
                } else {
                    int h = gcol >> 5, dd = gcol & 31;
                    int bb = grow >> 10, nn = grow & 1023;
                    float* p = Out + ((size_t)((bb * Hk + h) * Nk + nn)) * DHk + dd;
                    *(float2*)p = make_float2(tfr(v0), tfr(v1));
                }
            }
        }
}

#define LN_SMEM_BYTES (64 * 258 * 4)
__global__ void gemm_ln(const float* __restrict__ A, const float* __restrict__ Bw,
                        const float* __restrict__ bias, const float* __restrict__ R,
                        const float* __restrict__ gam, const float* __restrict__ bet,
                        float* __restrict__ Out, int K) {
    extern __shared__ float sm[];
    float* As = sm;
    float* Bs = sm + 2304;
    const int t = threadIdx.x, l = t & 31, wid = t >> 5;
    const int wm = wid & 1, wn = wid >> 1;
    const int mbase = blockIdx.x * 64;

    float acc[2][8][4];
#pragma unroll
    for (int mt = 0; mt < 2; mt++)
#pragma unroll
        for (int nt = 0; nt < 8; nt++)
#pragma unroll
            for (int i = 0; i < 4; i++) acc[mt][nt][i] = 0.f;

    for (int kc = 0; kc < K; kc += 32) {
#pragma unroll
        for (int i = 0; i < 2; i++) {
            int idx = t + i * 256;
            int r = idx >> 3, q = idx & 7;
            float4 v = *(const float4*)(A + (size_t)(mbase + r) * K + kc + q * 4);
            float* d = &As[r * 36 + q * 4];
            d[0] = tfr(v.x); d[1] = tfr(v.y); d[2] = tfr(v.z); d[3] = tfr(v.w);
        }
#pragma unroll
        for (int i = 0; i < 8; i++) {
            int idx = t + i * 256;
            int k = idx >> 6, q = idx & 63;
            float4 v = *(const float4*)(Bw + (size_t)(kc + k) * 256 + q * 4);
            float* d = &Bs[k * 264 + q * 4];
            d[0] = tfr(v.x); d[1] = tfr(v.y); d[2] = tfr(v.z); d[3] = tfr(v.w);
        }
        __syncthreads();
#pragma unroll
        for (int ks = 0; ks < 4; ks++) {
            unsigned a[2][4];
#pragma unroll
            for (int mt = 0; mt < 2; mt++) {
                const float* p = &As[(wm * 32 + mt * 16 + (l >> 2)) * 36 + ks * 8 + (l & 3)];
                a[mt][0] = FB(p[0]); a[mt][1] = FB(p[8 * 36]);
                a[mt][2] = FB(p[4]); a[mt][3] = FB(p[8 * 36 + 4]);
            }
#pragma unroll
            for (int nt = 0; nt < 8; nt++) {
                const float* p = &Bs[(ks * 8 + (l & 3)) * 264 + wn * 64 + nt * 8 + (l >> 2)];
                unsigned b0 = FB(p[0]), b1 = FB(p[4 * 264]);
                mma8(acc[0][nt], a[0], b0, b1);
                mma8(acc[1][nt], a[1], b0, b1);
            }
        }
        __syncthreads();
    }

    float* res = sm;
#pragma unroll
    for (int mt = 0; mt < 2; mt++)
#pragma unroll
        for (int nt = 0; nt < 8; nt++) {
            int m = wm * 32 + mt * 16 + (l >> 2);
            int n = wn * 64 + nt * 8 + (l & 3) * 2;
            *(float2*)&res[m * 258 + n] = make_float2(acc[mt][nt][0], acc[mt][nt][1]);
            *(float2*)&res[(m + 8) * 258 + n] = make_float2(acc[mt][nt][2], acc[mt][nt][3]);
        }
    __syncthreads();

#pragma unroll
    for (int i = 0; i < 8; i++) {
        int r = wid * 8 + i;
        int grow = mbase + r;
        float s = 0.f;
        for (int c = l; c < 256; c += 32) {
            float v = res[r * 258 + c] + R[(size_t)grow * 256 + c] + bias[c];
            res[r * 258 + c] = v;
            s += v;
        }
#pragma unroll
        for (int o = 16; o > 0; o >>= 1) s += __shfl_xor_sync(0xffffffffu, s, o);
        float mu = s * (1.f / 256.f);
        float s2 = 0.f;
        for (int c = l; c < 256; c += 32) { float dv = res[r * 258 + c] - mu; s2 += dv * dv; }
#pragma unroll
        for (int o = 16; o > 0; o >>= 1) s2 += __shfl_xor_sync(0xffffffffu, s2, o);
        float rs = rsqrtf(s2 * (1.f / 256.f) + 1e-5f);
        for (int c = l; c < 256; c += 32)
            Out[(size_t)grow * 256 + c] = (res[r * 258 + c] - mu) * rs * gam[c] + bet[c];
    }
}

// =====================================================================
// Fused attention, 2-pass online softmax + recompute (see R3 notes).
// =====================================================================
#define ATTN_SMEM_FLOATS (2304 + 3*4608 + 8448 + 512)   // 25088
#define ATTN_SMEM_BYTES  (ATTN_SMEM_FLOATS * 4)         // 100352

__global__ __launch_bounds__(256, 2)
void attn_kernel(const float* __restrict__ mask, float* __restrict__ attn_out) {
    extern __shared__ float sm[];
    float* Qs  = sm;                    // 2304
    float* Kb0 = sm + 2304;             // 4608 each
    float* Kb1 = Kb0 + 4608;
    float* Kb2 = Kb1 + 4608;
    float* Ps  = Kb2 + 4608;            // 8448
    float* st  = Ps + 8448;             // 512
    float* Kbuf[3] = {Kb0, Kb1, Kb2};

    const int t = threadIdx.x, l = t & 31, wid = t >> 5;
    const int wm = wid & 1, wn = wid >> 1;
    const int m0 = blockIdx.x * 64, h = blockIdx.y, b = blockIdx.z;

    const float* Qg  = g_Q + ((size_t)((b * Hk + h) * Nk + m0)) * DHk;
    const float* Kg  = g_K + ((size_t)((b * Hk + h) * Nk)) * DHk;
    const float* Vg  = g_V + ((size_t)((b * Hk + h) * Nk)) * DHk;
    const float* RBg = g_RB + ((size_t)(b * Nk + m0)) * Nk;
    const float* mkp = mask + b * Nk;
    const float scale = 0.17677669529663687f;

    // ---- prologue: Q + K0 (group0), K1 (group1) ----
#pragma unroll
    for (int i = 0; i < 2; i++) {
        int q = t + i * 256;
        int row = q >> 3, c4 = q & 7;
        cpa16(Qs + row * 36 + c4 * 4, Qg + q * 4);
    }
    load_chunk(Kb0, Kg, t); cpa_commit();
    load_chunk(Kb1, Kg + 4096, t); cpa_commit();
    cpa_wait<1>(); __syncthreads();

    float mL[4], lL[4];
#pragma unroll
    for (int r = 0; r < 4; r++) { mL[r] = -1e30f; lL[r] = 0.f; }

    // ================= PASS 1: stats =================
    for (int c = 0; c < 8; c++) {
        float* kb = Kbuf[c & 1];
        float acc[2][4][4];
#pragma unroll
        for (int mt = 0; mt < 2; mt++)
#pragma unroll
            for (int nt = 0; nt < 4; nt++)
#pragma unroll
                for (int i = 0; i < 4; i++) acc[mt][nt][i] = 0.f;

#pragma unroll
        for (int ks = 0; ks < 4; ks++) {
            unsigned aq[2][4];
#pragma unroll
            for (int mt = 0; mt < 2; mt++) {
                const float* p = &Qs[(wm * 32 + mt * 16 + (l >> 2)) * 36 + ks * 8 + (l & 3)];
                aq[mt][0] = FB(p[0]); aq[mt][1] = FB(p[8 * 36]);
                aq[mt][2] = FB(p[4]); aq[mt][3] = FB(p[8 * 36 + 4]);
            }
#pragma unroll
            for (int nt = 0; nt < 4; nt++) {
                const float* p = &kb[(wn * 32 + nt * 8 + (l >> 2)) * 36 + ks * 8 + (l & 3)];
                unsigned b0 = FB(p[0]), b1 = FB(p[4]);
                mma8(acc[0][nt], aq[0], b0, b1);
                mma8(acc[1][nt], aq[1], b0, b1);
            }
        }
        __syncthreads();                         // kb consumed
        if (c < 6) { load_chunk(Kbuf[c & 1], Kg + (size_t)(c + 2) * 4096, t); cpa_commit(); }

        float2 mk2[4];
#pragma unroll
        for (int nt = 0; nt < 4; nt++)
            mk2[nt] = *(const float2*)(mkp + c * 128 + wn * 32 + nt * 8 + (l & 3) * 2);

#pragma unroll
        for (int r = 0; r < 4; r++) {
            int row = wm * 32 + (r >> 1) * 16 + (r & 1) * 8 + (l >> 2);
            const float* rbrow = RBg + (size_t)row * Nk + c * 128 + wn * 32;
            float vs[8], vmax = -1e30f;
#pragma unroll
            for (int nt = 0; nt < 4; nt++) {
                float2 rb2 = *(const float2*)(rbrow + nt * 8 + (l & 3) * 2);
                int ai = (r & 1) * 2;
                float s0 = acc[r >> 1][nt][ai] * scale + rb2.x;
                float s1 = acc[r >> 1][nt][ai + 1] * scale + rb2.y;
                if (!(mk2[nt].x > 0.f)) s0 = -1e9f;
                if (!(mk2[nt].y > 0.f)) s1 = -1e9f;
                vs[nt * 2] = s0; vs[nt * 2 + 1] = s1;
                vmax = fmaxf(vmax, fmaxf(s0, s1));
            }
            float mn = fmaxf(mL[r], vmax);
            float lsum = lL[r] * __expf(mL[r] - mn);
#pragma unroll
            for (int k = 0; k < 8; k++) lsum += __expf(vs[k] - mn);
            mL[r] = mn; lL[r] = lsum;
        }
        if (c < 6) cpa_wait<1>(); else cpa_wait<0>();
        __syncthreads();
    }

    // ---- merge stats ----
#pragma unroll
    for (int r = 0; r < 4; r++) {
        float m = mL[r], lv = lL[r];
#pragma unroll
        for (int o = 1; o <= 2; o <<= 1) {
            float m2 = __shfl_xor_sync(0xffffffffu, m, o);
            float l2 = __shfl_xor_sync(0xffffffffu, lv, o);
            float mn = fmaxf(m, m2);
            lv = lv * __expf(m - mn) + l2 * __expf(m2 - mn);
            m = mn;
        }
        if ((l & 3) == 0) {
            int row = wm * 32 + (r >> 1) * 16 + (r & 1) * 8 + (l >> 2);
            st[(row * 4 + wn) * 2]     = m;
            st[(row * 4 + wn) * 2 + 1] = lv;
        }
    }
    __syncthreads();
    float mF[4], ilF[4];
#pragma unroll
    for (int r = 0; r < 4; r++) {
        int row = wm * 32 + (r >> 1) * 16 + (r & 1) * 8 + (l >> 2);
        float m = -1e30f, lv = 0.f;
#pragma unroll
        for (int w2 = 0; w2 < 4; w2++) {
            float m2 = st[(row * 4 + w2) * 2];
            float l2 = st[(row * 4 + w2) * 2 + 1];
            float mn = fmaxf(m, m2);
            lv = lv * __expf(m - mn) + l2 * __expf(m2 - mn);
            m = mn;
        }
        mF[r] = m; ilF[r] = 1.f / lv;
    }

    // ---- pass 2 prologue ----
    load_chunk(Kb0, Kg, t); cpa_commit();
    load_chunk(Kb1, Vg, t); cpa_commit();
    load_chunk(Kb2, Kg + 4096, t); cpa_commit();
    cpa_wait<2>(); __syncthreads();

    float accY[2][4];
#pragma unroll
    for (int mt = 0; mt < 2; mt++)
#pragma unroll
        for (int i = 0; i < 4; i++) accY[mt][i] = 0.f;

    // ================= PASS 2 =================
    for (int c = 0; c < 8; c++) {
        float* kb = Kbuf[(2 * c) % 3];
        float* vb = Kbuf[(2 * c + 1) % 3];

        float acc[2][4][4];
#pragma unroll
        for (int mt = 0; mt < 2; mt++)
#pragma unroll
            for (int nt = 0; nt < 4; nt++)
#pragma unroll
                for (int i = 0; i < 4; i++) acc[mt][nt][i] = 0.f;

#pragma unroll
        for (int ks = 0; ks < 4; ks++) {
            unsigned aq[2][4];
#pragma unroll
            for (int mt = 0; mt < 2; mt++) {
                const float* p = &Qs[(wm * 32 + mt * 16 + (l >> 2)) * 36 + ks * 8 + (l & 3)];
                aq[mt][0] = FB(p[0]); aq[mt][1] = FB(p[8 * 36]);
                aq[mt][2] = FB(p[4]); aq[mt][3] = FB(p[8 * 36 + 4]);
            }
#pragma unroll
            for (int nt = 0; nt < 4; nt++) {
                const float* p = &kb[(wn * 32 + nt * 8 + (l >> 2)) * 36 + ks * 8 + (l & 3)];
                unsigned b0 = FB(p[0]), b1 = FB(p[4]);
                mma8(acc[0][nt], aq[0], b0, b1);
                mma8(acc[1][nt], aq[1], b0, b1);
            }
        }

        float2 mk2[4];
#pragma unroll
        for (int nt = 0; nt < 4; nt++)
            mk2[nt] = *(const float2*)(mkp + c * 128 + wn * 32 + nt * 8 + (l & 3) * 2);

#pragma unroll
        for (int r = 0; r < 4; r++) {
            int row = wm * 32 + (r >> 1) * 16 + (r & 1) * 8 + (l >> 2);
            const float* rbrow = RBg + (size_t)row * Nk + c * 128 + wn * 32;
            float* arow = attn_out + (((size_t)((b * Hk + h) * Nk + m0 + row)) * Nk)
                          + c * 128 + wn * 32;
#pragma unroll
            for (int nt = 0; nt < 4; nt++) {
                float2 rb2 = *(const float2*)(rbrow + nt * 8 + (l & 3) * 2);
                int ai = (r & 1) * 2;
                float s0 = acc[r >> 1][nt][ai] * scale + rb2.x;
                float s1 = acc[r >> 1][nt][ai + 1] * scale + rb2.y;
                if (!(mk2[nt].x > 0.f)) s0 = -1e9f;
                if (!(mk2[nt].y > 0.f)) s1 = -1e9f;
                float p0 = __expf(s0 - mF[r]) * ilF[r];
                float p1 = __expf(s1 - mF[r]) * ilF[r];
                *(float2*)(arow + nt * 8 + (l & 3) * 2) = make_float2(p0, p1);
                *(float2*)&Ps[row * 132 + wn * 32 + nt * 8 + (l & 3) * 2] =
                    make_float2(tfr(p0), tfr(p1));
            }
        }
        if (c < 7) cpa_wait<1>(); else cpa_wait<0>();  // V(c) done
        __syncthreads();                                // Ps + V(c) visible, kb free
        if (c < 7) { load_chunk(kb, Vg + (size_t)(c + 1) * 4096, t); cpa_commit(); }

        // ---- P@V ----
#pragma unroll
        for (int ks = 0; ks < 16; ks++) {
            unsigned a0[4], a1[4];
            {
                const float* p = &Ps[(wm * 32 + (l >> 2)) * 132 + ks * 8 + (l & 3)];
                a0[0] = FB(p[0]); a0[1] = FB(p[8 * 132]);
                a0[2] = FB(p[4]); a0[3] = FB(p[8 * 132 + 4]);
                const float* q = p + 16 * 132;
                a1[0] = FB(q[0]); a1[1] = FB(q[8 * 132]);
                a1[2] = FB(q[4]); a1[3] = FB(q[8 * 132 + 4]);
            }
            const float* pb = &vb[(ks * 8 + (l & 3)) * 36 + wn * 8 + (l >> 2)];
            unsigned b0 = FB(pb[0]), b1 = FB(pb[4 * 36]);
            mma8(accY[0], a0, b0, b1);
            mma8(accY[1], a1, b0, b1);
        }
        if (c < 7) cpa_wait<1>(); else cpa_wait<0>();  // K(c+1) done
        __syncthreads();                                // vb free
        if (c < 6) { load_chunk(vb, Kg + (size_t)(c + 2) * 4096, t); cpa_commit(); }
    }

    // ---- write Y ----
#pragma unroll
    for (int mt = 0; mt < 2; mt++) {
        int row = m0 + wm * 32 + mt * 16 + (l >> 2);
        int d = wn * 8 + (l & 3) * 2;
        float* yp = g_Y + ((size_t)(b * Nk + row)) * Dk + h * DHk + d;
        *(float2*)yp = make_float2(accY[mt][0], accY[mt][1]);
        *(float2*)(yp + 8 * Dk) = make_float2(accY[mt][2], accY[mt][3]);
    }
}

// ---------------- launch ----------------
extern "C" void kernel_launch(void* const* d_in, const int* in_sizes, int n_in,
                              void* d_out, int out_size) {
    const float* X    = (const float*)d_in[0];
    const float* mask = (const float*)d_in[1];
    const float* adj  = (const float*)d_in[2];
    const float* attr = (const float*)d_in[3];
    const float* rep  = (const float*)d_in[4];
    const float* Wq = (const float*)d_in[5];  const float* bq = (const float*)d_in[6];
    const float* Wk = (const float*)d_in[7];  const float* bk = (const float*)d_in[8];
    const float* Wv = (const float*)d_in[9];  const float* bv = (const float*)d_in[10];
    const float* Wo = (const float*)d_in[11]; const float* bo = (const float*)d_in[12];
    const float* Wf1 = (const float*)d_in[13]; const float* bf1 = (const float*)d_in[14];
    const float* Wf2 = (const float*)d_in[15]; const float* bf2 = (const float*)d_in[16];
    const float* g1 = (const float*)d_in[17]; const float* b1 = (const float*)d_in[18];
    const float* g2 = (const float*)d_in[19]; const float* b2 = (const float*)d_in[20];

    float* out = (float*)d_out;
    float* attn_out = out + (size_t)BN * Dk;

    cudaFuncSetAttribute(attn_kernel, cudaFuncAttributeMaxDynamicSharedMemorySize,
                         ATTN_SMEM_BYTES);
    cudaFuncSetAttribute(gemm_ln, cudaFuncAttributeMaxDynamicSharedMemorySize,
                         LN_SMEM_BYTES);

    float* gq; cudaGetSymbolAddress((void**)&gq, g_Q);
    float* gk; cudaGetSymbolAddress((void**)&gk, g_K);
    float* gv; cudaGetSymbolAddress((void**)&gv, g_V);
    float* gy; cudaGetSymbolAddress((void**)&gy, g_Y);
    float* gx1; cudaGetSymbolAddress((void**)&gx1, g_X1);
    float* ghb; cudaGetSymbolAddress((void**)&ghb, g_Hb);

    gemm_plain<1><<<dim3(64, 4), 256>>>(X, Wq, bq, gq, 256, 256);
    gemm_plain<1><<<dim3(64, 4), 256>>>(X, Wk, bk, gk, 256, 256);
    gemm_plain<1><<<dim3(64, 4), 256>>>(X, Wv, bv, gv, 256, 256);
    bias_kernel<<<8192, 256>>>((const float4*)adj, (const float4*)attr, (const float4*)rep);

    attn_kernel<<<dim3(16, Hk, Bk), 256, ATTN_SMEM_BYTES>>>(mask, attn_out);

    gemm_ln<<<128, 256, LN_SMEM_BYTES>>>(gy, Wo, bo, X, g1, b1, gx1, 256);
    gemm_plain<0><<<dim3(64, 16), 256>>>(gx1, Wf1, bf1, ghb, 256, 1024);
    gemm_ln<<<128, 256, LN_SMEM_BYTES>>>(ghb, Wf2, bf2, gx1, g2, b2, out, 1024);
}

// round 8
// speedup vs baseline: 2.5767x; 1.0405x over previous
#include <cuda_runtime.h>
#include <math.h>
#include <stdint.h>

#define Bk   8
#define Nk   1024
#define Dk   256
#define Hk   8
#define DHk  32
#define DFFk 1024
#define BN   (Bk*Nk)   // 8192

// ---------------- scratch ----------------
__device__ float g_Q [Bk*Hk*Nk*DHk];
__device__ float g_K [Bk*Hk*Nk*DHk];
__device__ float g_V [Bk*Hk*Nk*DHk];
__device__ float g_Y [BN*Dk];
__device__ float g_X1[BN*Dk];
__device__ float g_Hb[(size_t)BN*DFFk];
__device__ float g_RB[(size_t)Bk*Nk*Nk];

// ---------------- helpers ----------------
__device__ __forceinline__ float tfr(float x) {
    unsigned u; asm("cvt.rna.tf32.f32 %0, %1;" : "=r"(u) : "f"(x));
    return __uint_as_float(u);
}
__device__ __forceinline__ unsigned FB(float x) { return __float_as_uint(x); }

__device__ __forceinline__ void mma8(float* d, const unsigned* a, unsigned b0, unsigned b1) {
    asm volatile("mma.sync.aligned.m16n8k8.row.col.f32.tf32.tf32.f32 "
        "{%0,%1,%2,%3},{%4,%5,%6,%7},{%8,%9},{%0,%1,%2,%3};"
        : "+f"(d[0]), "+f"(d[1]), "+f"(d[2]), "+f"(d[3])
        : "r"(a[0]), "r"(a[1]), "r"(a[2]), "r"(a[3]), "r"(b0), "r"(b1));
}

__device__ __forceinline__ void cpa16(void* s, const void* g) {
    uint32_t sa = (uint32_t)__cvta_generic_to_shared(s);
    asm volatile("cp.async.cg.shared.global [%0], [%1], 16;" :: "r"(sa), "l"(g));
}
__device__ __forceinline__ void cpa_commit() { asm volatile("cp.async.commit_group;"); }
template<int N> __device__ __forceinline__ void cpa_wait() {
    asm volatile("cp.async.wait_group %0;" :: "n"(N));
}

// load a 128x32 float chunk into smem with pad-36 rows
__device__ __forceinline__ void load_chunk(float* buf, const float* src, int t) {
#pragma unroll
    for (int i = 0; i < 4; i++) {
        int q = t + i * 256;
        int row = q >> 3, c4 = q & 7;
        cpa16(buf + row * 36 + c4 * 4, src + q * 4);
    }
}

// ---------------- kernel: rel_bias = adj + attr + rep ----------------
__global__ void bias_kernel(const float4* __restrict__ a, const float4* __restrict__ b,
                            const float4* __restrict__ c) {
    int i = blockIdx.x * blockDim.x + threadIdx.x;
    float4 x = a[i], y = b[i], z = c[i];
    float4 o;
    o.x = x.x + y.x + z.x; o.y = x.y + y.y + z.y;
    o.z = x.z + y.z + z.z; o.w = x.w + y.w + z.w;
    ((float4*)g_RB)[i] = o;
}

// =====================================================================
// gemm_plain: MODE 0 = relu+bias write (ffn1); MODE 1 = fused QKV
// =====================================================================
struct QKVArgs { const float* W[3]; const float* b[3]; float* O[3]; };

template<int MODE>
__global__ void gemm_plain(const float* __restrict__ A, const float* __restrict__ Bw_,
                           const float* __restrict__ bias_, float* __restrict__ Out_,
                           int K, int NTOT, QKVArgs qa) {
    __shared__ float As[128][36];
    __shared__ float Bs[32][72];
    const int t = threadIdx.x, l = t & 31, wid = t >> 5;
    const int wm = wid & 3, wn = wid >> 2;
    const int mbase = blockIdx.x * 128, nbase = blockIdx.y * 64;

    const float* Bw  = (MODE == 1) ? qa.W[blockIdx.z] : Bw_;
    const float* bias= (MODE == 1) ? qa.b[blockIdx.z] : bias_;
    float* Out       = (MODE == 1) ? qa.O[blockIdx.z] : Out_;

    float acc[2][4][4];
#pragma unroll
    for (int mt = 0; mt < 2; mt++)
#pragma unroll
        for (int nt = 0; nt < 4; nt++)
#pragma unroll
            for (int i = 0; i < 4; i++) acc[mt][nt][i] = 0.f;

    for (int kc = 0; kc < K; kc += 32) {
#pragma unroll
        for (int i = 0; i < 4; i++) {
            int idx = t + i * 256;
            int r = idx >> 3, q = idx & 7;
            float4 v = *(const float4*)(A + (size_t)(mbase + r) * K + kc + q * 4);
            float* d = &As[r][q * 4];
            d[0] = tfr(v.x); d[1] = tfr(v.y); d[2] = tfr(v.z); d[3] = tfr(v.w);
        }
#pragma unroll
        for (int i = 0; i < 2; i++) {
            int idx = t + i * 256;
            int k = idx >> 4, q = idx & 15;
            float4 v = *(const float4*)(Bw + (size_t)(kc + k) * NTOT + nbase + q * 4);
            float* d = &Bs[k][q * 4];
            d[0] = tfr(v.x); d[1] = tfr(v.y); d[2] = tfr(v.z); d[3] = tfr(v.w);
        }
        __syncthreads();
#pragma unroll
        for (int ks = 0; ks < 4; ks++) {
            unsigned a[2][4];
#pragma unroll
            for (int mt = 0; mt < 2; mt++) {
                const float* p = &As[wm * 32 + mt * 16 + (l >> 2)][ks * 8 + (l & 3)];
                a[mt][0] = FB(p[0]); a[mt][1] = FB(p[8 * 36]);
                a[mt][2] = FB(p[4]); a[mt][3] = FB(p[8 * 36 + 4]);
            }
#pragma unroll
            for (int nt = 0; nt < 4; nt++) {
                const float* p = &Bs[ks * 8 + (l & 3)][wn * 32 + nt * 8 + (l >> 2)];
                unsigned b0 = FB(p[0]), b1 = FB(p[4 * 72]);
                mma8(acc[0][nt], a[0], b0, b1);
                mma8(acc[1][nt], a[1], b0, b1);
            }
        }
        __syncthreads();
    }

#pragma unroll
    for (int mt = 0; mt < 2; mt++)
#pragma unroll
        for (int nt = 0; nt < 4; nt++) {
            int gcol = nbase + wn * 32 + nt * 8 + (l & 3) * 2;
            float bb0 = bias[gcol], bb1 = bias[gcol + 1];
#pragma unroll
            for (int half = 0; half < 2; half++) {
                int grow = mbase + wm * 32 + mt * 16 + (l >> 2) + half * 8;
                float v0 = acc[mt][nt][half * 2 + 0] + bb0;
                float v1 = acc[mt][nt][half * 2 + 1] + bb1;
                if (MODE == 0) {
                    *(float2*)(Out + (size_t)grow * NTOT + gcol) =
                        make_float2(fmaxf(v0, 0.f), fmaxf(v1, 0.f));
                } else {
                    int h = gcol >> 5, dd = gcol & 31;
                    int bb = grow >> 10, nn = grow & 1023;
                    float* p = Out + ((size_t)((bb * Hk + h) * Nk + nn)) * DHk + dd;
                    *(float2*)p = make_float2(tfr(v0), tfr(v1));
                }
            }
        }
}

#define LN_SMEM_BYTES (64 * 258 * 4)
__global__ void gemm_ln(const float* __restrict__ A, const float* __restrict__ Bw,
                        const float* __restrict__ bias, const float* __restrict__ R,
                        const float* __restrict__ gam, const float* __restrict__ bet,
                        float* __restrict__ Out, int K) {
    extern __shared__ float sm[];
    float* As = sm;
    float* Bs = sm + 2304;
    const int t = threadIdx.x, l = t & 31, wid = t >> 5;
    const int wm = wid & 1, wn = wid >> 1;
    const int mbase = blockIdx.x * 64;

    float acc[2][8][4];
#pragma unroll
    for (int mt = 0; mt < 2; mt++)
#pragma unroll
        for (int nt = 0; nt < 8; nt++)
#pragma unroll
            for (int i = 0; i < 4; i++) acc[mt][nt][i] = 0.f;

    for (int kc = 0; kc < K; kc += 32) {
#pragma unroll
        for (int i = 0; i < 2; i++) {
            int idx = t + i * 256;
            int r = idx >> 3, q = idx & 7;
            float4 v = *(const float4*)(A + (size_t)(mbase + r) * K + kc + q * 4);
            float* d = &As[r * 36 + q * 4];
            d[0] = tfr(v.x); d[1] = tfr(v.y); d[2] = tfr(v.z); d[3] = tfr(v.w);
        }
#pragma unroll
        for (int i = 0; i < 8; i++) {
            int idx = t + i * 256;
            int k = idx >> 6, q = idx & 63;
            float4 v = *(const float4*)(Bw + (size_t)(kc + k) * 256 + q * 4);
            float* d = &Bs[k * 264 + q * 4];
            d[0] = tfr(v.x); d[1] = tfr(v.y); d[2] = tfr(v.z); d[3] = tfr(v.w);
        }
        __syncthreads();
#pragma unroll
        for (int ks = 0; ks < 4; ks++) {
            unsigned a[2][4];
#pragma unroll
            for (int mt = 0; mt < 2; mt++) {
                const float* p = &As[(wm * 32 + mt * 16 + (l >> 2)) * 36 + ks * 8 + (l & 3)];
                a[mt][0] = FB(p[0]); a[mt][1] = FB(p[8 * 36]);
                a[mt][2] = FB(p[4]); a[mt][3] = FB(p[8 * 36 + 4]);
            }
#pragma unroll
            for (int nt = 0; nt < 8; nt++) {
                const float* p = &Bs[(ks * 8 + (l & 3)) * 264 + wn * 64 + nt * 8 + (l >> 2)];
                unsigned b0 = FB(p[0]), b1 = FB(p[4 * 264]);
                mma8(acc[0][nt], a[0], b0, b1);
                mma8(acc[1][nt], a[1], b0, b1);
            }
        }
        __syncthreads();
    }

    float* res = sm;
#pragma unroll
    for (int mt = 0; mt < 2; mt++)
#pragma unroll
        for (int nt = 0; nt < 8; nt++) {
            int m = wm * 32 + mt * 16 + (l >> 2);
            int n = wn * 64 + nt * 8 + (l & 3) * 2;
            *(float2*)&res[m * 258 + n] = make_float2(acc[mt][nt][0], acc[mt][nt][1]);
            *(float2*)&res[(m + 8) * 258 + n] = make_float2(acc[mt][nt][2], acc[mt][nt][3]);
        }
    __syncthreads();

#pragma unroll
    for (int i = 0; i < 8; i++) {
        int r = wid * 8 + i;
        int grow = mbase + r;
        float s = 0.f;
        for (int c = l; c < 256; c += 32) {
            float v = res[r * 258 + c] + R[(size_t)grow * 256 + c] + bias[c];
            res[r * 258 + c] = v;
            s += v;
        }
#pragma unroll
        for (int o = 16; o > 0; o >>= 1) s += __shfl_xor_sync(0xffffffffu, s, o);
        float mu = s * (1.f / 256.f);
        float s2 = 0.f;
        for (int c = l; c < 256; c += 32) { float dv = res[r * 258 + c] - mu; s2 += dv * dv; }
#pragma unroll
        for (int o = 16; o > 0; o >>= 1) s2 += __shfl_xor_sync(0xffffffffu, s2, o);
        float rs = rsqrtf(s2 * (1.f / 256.f) + 1e-5f);
        for (int c = l; c < 256; c += 32)
            Out[(size_t)grow * 256 + c] = (res[r * 258 + c] - mu) * rs * gam[c] + bet[c];
    }
}

// =====================================================================
// Fused attention, 2-pass online softmax + recompute.
// Register-resident P, warp-local P@V, 1 barrier/chunk, tiered cp.async
// waits.  Z-reduction stride 34 (even -> aligned float2).
// =====================================================================
#define ATTN_SMEM_FLOATS (2304 + 4*4608 + 512)
#define ATTN_SMEM_BYTES  (ATTN_SMEM_FLOATS * 4)
#define ZSTRIDE 34
#define ZSLOT   (64 * ZSTRIDE)   // 2176

__global__ __launch_bounds__(256, 2)
void attn_kernel(const float* __restrict__ mask, float* __restrict__ attn_out) {
    extern __shared__ float sm[];
    float* Qs = sm;                      // 2304
    float* Kb[4] = { sm + 2304, sm + 2304 + 4608, sm + 2304 + 2*4608, sm + 2304 + 3*4608 };
    float* st = sm + 2304 + 4*4608;      // 512

    const int t = threadIdx.x, l = t & 31, wid = t >> 5;
    const int wm = wid & 1, wn = wid >> 1;
    const int m0 = blockIdx.x * 64, h = blockIdx.y, b = blockIdx.z;

    const float* Qg  = g_Q + ((size_t)((b * Hk + h) * Nk + m0)) * DHk;
    const float* Kg  = g_K + ((size_t)((b * Hk + h) * Nk)) * DHk;
    const float* Vg  = g_V + ((size_t)((b * Hk + h) * Nk)) * DHk;
    const float* RBg = g_RB + ((size_t)(b * Nk + m0)) * Nk;
    const float* mkp = mask + b * Nk;
    const float scale = 0.17677669529663687f;

    // ---- prologue: G0={Q,K0}, G1={K1}, G2={K2} ----
#pragma unroll
    for (int i = 0; i < 2; i++) {
        int q = t + i * 256;
        cpa16(Qs + (q >> 3) * 36 + (q & 7) * 4, Qg + q * 4);
    }
    load_chunk(Kb[0], Kg, t); cpa_commit();
    load_chunk(Kb[1], Kg + 4096, t); cpa_commit();
    load_chunk(Kb[2], Kg + 2 * 4096, t); cpa_commit();

    float mL[4], lL[4];
#pragma unroll
    for (int r = 0; r < 4; r++) { mL[r] = -1e30f; lL[r] = 0.f; }

    // ================= PASS 1: stats (1 barrier/chunk) =================
    // groups: g0..g2 prologue, g3..g7 at c=0..4. chunk c lives in group g_c.
    // allowed-pending at c = 3+min(c,5)-(c+1):  c<=5 -> 2, c==6 -> 1, c==7 -> 0.
    for (int c = 0; c < 8; c++) {
        if (c < 6)       cpa_wait<2>();
        else if (c == 6) cpa_wait<1>();
        else             cpa_wait<0>();
        __syncthreads();                 // chunk c ready; buffer (c+3)&3 free
        if (c < 5) { load_chunk(Kb[(c + 3) & 3], Kg + (size_t)(c + 3) * 4096, t); cpa_commit(); }

        float* kb = Kb[c & 3];
        float acc[2][4][4];
#pragma unroll
        for (int mt = 0; mt < 2; mt++)
#pragma unroll
            for (int nt = 0; nt < 4; nt++)
#pragma unroll
                for (int i = 0; i < 4; i++) acc[mt][nt][i] = 0.f;

#pragma unroll
        for (int ks = 0; ks < 4; ks++) {
            unsigned aq[2][4];
#pragma unroll
            for (int mt = 0; mt < 2; mt++) {
                const float* p = &Qs[(wm * 32 + mt * 16 + (l >> 2)) * 36 + ks * 8 + (l & 3)];
                aq[mt][0] = FB(p[0]); aq[mt][1] = FB(p[8 * 36]);
                aq[mt][2] = FB(p[4]); aq[mt][3] = FB(p[8 * 36 + 4]);
            }
#pragma unroll
            for (int nt = 0; nt < 4; nt++) {
                const float* p = &kb[(wn * 32 + nt * 8 + (l >> 2)) * 36 + ks * 8 + (l & 3)];
                unsigned b0 = FB(p[0]), b1 = FB(p[4]);
                mma8(acc[0][nt], aq[0], b0, b1);
                mma8(acc[1][nt], aq[1], b0, b1);
            }
        }

        float2 mk2[4];
#pragma unroll
        for (int nt = 0; nt < 4; nt++)
            mk2[nt] = *(const float2*)(mkp + c * 128 + wn * 32 + nt * 8 + (l & 3) * 2);

#pragma unroll
        for (int r = 0; r < 4; r++) {
            int row = wm * 32 + (r >> 1) * 16 + (r & 1) * 8 + (l >> 2);
            const float* rbrow = RBg + (size_t)row * Nk + c * 128 + wn * 32;
            float vs[8], vmax = -1e30f;
#pragma unroll
            for (int nt = 0; nt < 4; nt++) {
                float2 rb2 = *(const float2*)(rbrow + nt * 8 + (l & 3) * 2);
                int ai = (r & 1) * 2;
                float s0 = acc[r >> 1][nt][ai] * scale + rb2.x;
                float s1 = acc[r >> 1][nt][ai + 1] * scale + rb2.y;
                if (!(mk2[nt].x > 0.f)) s0 = -1e9f;
                if (!(mk2[nt].y > 0.f)) s1 = -1e9f;
                vs[nt * 2] = s0; vs[nt * 2 + 1] = s1;
                vmax = fmaxf(vmax, fmaxf(s0, s1));
            }
            float mn = fmaxf(mL[r], vmax);
            float lsum = lL[r] * __expf(mL[r] - mn);
#pragma unroll
            for (int k = 0; k < 8; k++) lsum += __expf(vs[k] - mn);
            mL[r] = mn; lL[r] = lsum;
        }
    }

    // ---- merge stats ----
#pragma unroll
    for (int r = 0; r < 4; r++) {
        float m = mL[r], lv = lL[r];
#pragma unroll
        for (int o = 1; o <= 2; o <<= 1) {
            float m2 = __shfl_xor_sync(0xffffffffu, m, o);
            float l2 = __shfl_xor_sync(0xffffffffu, lv, o);
            float mn = fmaxf(m, m2);
            lv = lv * __expf(m - mn) + l2 * __expf(m2 - mn);
            m = mn;
        }
        if ((l & 3) == 0) {
            int row = wm * 32 + (r >> 1) * 16 + (r & 1) * 8 + (l >> 2);
            st[(row * 4 + wn) * 2]     = m;
            st[(row * 4 + wn) * 2 + 1] = lv;
        }
    }
    __syncthreads();
    float mF[4], ilF[4];
#pragma unroll
    for (int r = 0; r < 4; r++) {
        int row = wm * 32 + (r >> 1) * 16 + (r & 1) * 8 + (l >> 2);
        float m = -1e30f, lv = 0.f;
#pragma unroll
        for (int w2 = 0; w2 < 4; w2++) {
            float m2 = st[(row * 4 + w2) * 2];
            float l2 = st[(row * 4 + w2) * 2 + 1];
            float mn = fmaxf(m, m2);
            lv = lv * __expf(m - mn) + l2 * __expf(m2 - mn);
            m = mn;
        }
        mF[r] = m; ilF[r] = 1.f / lv;
    }
    __syncthreads();   // everyone done reading st / pass-1 buffers

    // ---- pass 2 prologue: pair0 = {K0,V0} ----
    load_chunk(Kb[0], Kg, t);
    load_chunk(Kb[1], Vg, t);
    cpa_commit();

    float Yacc[2][4][4];
#pragma unroll
    for (int mt = 0; mt < 2; mt++)
#pragma unroll
        for (int g = 0; g < 4; g++)
#pragma unroll
            for (int i = 0; i < 4; i++) Yacc[mt][g][i] = 0.f;

    const int rlane = l & 3;
    const int lbase = l & ~3;
    const int slo = lbase | (rlane >> 1);
    const int shi = lbase | ((rlane >> 1) + 2);
    const bool odd = (rlane & 1) != 0;

    // ================= PASS 2 (1 barrier/chunk) =================
    for (int c = 0; c < 8; c++) {
        cpa_wait<0>();
        __syncthreads();                 // pair c&1 ready; pair (c+1)&1 free
        if (c < 7) {
            load_chunk(Kb[2 * ((c + 1) & 1)],     Kg + (size_t)(c + 1) * 4096, t);
            load_chunk(Kb[2 * ((c + 1) & 1) + 1], Vg + (size_t)(c + 1) * 4096, t);
            cpa_commit();
        }
        float* kb = Kb[2 * (c & 1)];
        float* vb = Kb[2 * (c & 1) + 1];

        // ---- QK^T ----
        float acc[2][4][4];
#pragma unroll
        for (int mt = 0; mt < 2; mt++)
#pragma unroll
            for (int nt = 0; nt < 4; nt++)
#pragma unroll
                for (int i = 0; i < 4; i++) acc[mt][nt][i] = 0.f;

#pragma unroll
        for (int ks = 0; ks < 4; ks++) {
            unsigned aq[2][4];
#pragma unroll
            for (int mt = 0; mt < 2; mt++) {
                const float* p = &Qs[(wm * 32 + mt * 16 + (l >> 2)) * 36 + ks * 8 + (l & 3)];
                aq[mt][0] = FB(p[0]); aq[mt][1] = FB(p[8 * 36]);
                aq[mt][2] = FB(p[4]); aq[mt][3] = FB(p[8 * 36 + 4]);
            }
#pragma unroll
            for (int nt = 0; nt < 4; nt++) {
                const float* p = &kb[(wn * 32 + nt * 8 + (l >> 2)) * 36 + ks * 8 + (l & 3)];
                unsigned b0 = FB(p[0]), b1 = FB(p[4]);
                mma8(acc[0][nt], aq[0], b0, b1);
                mma8(acc[1][nt], aq[1], b0, b1);
            }
        }

        // ---- softmax-normalize, write attn, keep tf32 P in regs ----
        float2 mk2[4];
#pragma unroll
        for (int nt = 0; nt < 4; nt++)
            mk2[nt] = *(const float2*)(mkp + c * 128 + wn * 32 + nt * 8 + (l & 3) * 2);

#pragma unroll
        for (int r = 0; r < 4; r++) {
            int row = wm * 32 + (r >> 1) * 16 + (r & 1) * 8 + (l >> 2);
            const float* rbrow = RBg + (size_t)row * Nk + c * 128 + wn * 32;
            float* arow = attn_out + (((size_t)((b * Hk + h) * Nk + m0 + row)) * Nk)
                          + c * 128 + wn * 32;
#pragma unroll
            for (int nt = 0; nt < 4; nt++) {
                float2 rb2 = *(const float2*)(rbrow + nt * 8 + (l & 3) * 2);
                int ai = (r & 1) * 2;
                float s0 = acc[r >> 1][nt][ai] * scale + rb2.x;
                float s1 = acc[r >> 1][nt][ai + 1] * scale + rb2.y;
                if (!(mk2[nt].x > 0.f)) s0 = -1e9f;
                if (!(mk2[nt].y > 0.f)) s1 = -1e9f;
                float p0 = __expf(s0 - mF[r]) * ilF[r];
                float p1 = __expf(s1 - mF[r]) * ilF[r];
                *(float2*)(arow + nt * 8 + (l & 3) * 2) = make_float2(p0, p1);
                acc[r >> 1][nt][ai]     = tfr(p0);   // keep P in regs
                acc[r >> 1][nt][ai + 1] = tfr(p1);
            }
        }

        // ---- P@V (warp-local k-slice, register A-fragments) ----
#pragma unroll
        for (int mt = 0; mt < 2; mt++)
#pragma unroll
            for (int nt = 0; nt < 4; nt++) {
                float c0 = acc[mt][nt][0], c1 = acc[mt][nt][1];
                float c2 = acc[mt][nt][2], c3 = acc[mt][nt][3];
                float v00 = __shfl_sync(0xffffffffu, c0, slo);
                float v01 = __shfl_sync(0xffffffffu, c1, slo);
                float v02 = __shfl_sync(0xffffffffu, c2, slo);
                float v03 = __shfl_sync(0xffffffffu, c3, slo);
                float v10 = __shfl_sync(0xffffffffu, c0, shi);
                float v11 = __shfl_sync(0xffffffffu, c1, shi);
                float v12 = __shfl_sync(0xffffffffu, c2, shi);
                float v13 = __shfl_sync(0xffffffffu, c3, shi);
                unsigned afr[4];
                afr[0] = FB(odd ? v01 : v00);   // (row,   k)
                afr[1] = FB(odd ? v03 : v02);   // (row+8, k)
                afr[2] = FB(odd ? v11 : v10);   // (row,   k+4)
                afr[3] = FB(odd ? v13 : v12);   // (row+8, k+4)
#pragma unroll
                for (int g = 0; g < 4; g++) {
                    const float* pv = &vb[(wn * 32 + nt * 8 + (l & 3)) * 36 + g * 8 + (l >> 2)];
                    unsigned b0 = FB(pv[0]), b1 = FB(pv[4 * 36]);
                    mma8(Yacc[mt][g], afr, b0, b1);
                }
            }
    }

    // ---- final cross-warp Y reduction (Z overlays Kb[0..1], stride 34) ----
    float* Z = Kb[0];                    // 4 slots x 64 x 34 = 8704 floats (fits 9216)
    __syncthreads();
#pragma unroll
    for (int mt = 0; mt < 2; mt++)
#pragma unroll
        for (int g = 0; g < 4; g++) {
            int row = wm * 32 + mt * 16 + (l >> 2);
            int col = g * 8 + (l & 3) * 2;
            float* zp = Z + wn * ZSLOT + row * ZSTRIDE + col;
            *(float2*)zp = make_float2(Yacc[mt][g][0], Yacc[mt][g][1]);
            *(float2*)(zp + 8 * ZSTRIDE) = make_float2(Yacc[mt][g][2], Yacc[mt][g][3]);
        }
    __syncthreads();

#pragma unroll
    for (int j = 0; j < 4; j++) {
        int e2 = t * 4 + j;              // 1024 float2 elements
        int row = e2 >> 4, col = (e2 & 15) * 2;
        const float* zp = Z + row * ZSTRIDE + col;
        float2 z0 = *(const float2*)(zp);
        float2 z1 = *(const float2*)(zp + ZSLOT);
        float2 z2 = *(const float2*)(zp + 2 * ZSLOT);
        float2 z3 = *(const float2*)(zp + 3 * ZSLOT);
        float y0 = z0.x + z1.x + z2.x + z3.x;
        float y1 = z0.y + z1.y + z2.y + z3.y;
        float* yp = g_Y + ((size_t)(b * Nk + m0 + row)) * Dk + h * DHk + col;
        *(float2*)yp = make_float2(y0, y1);
    }
}

// ---------------- launch ----------------
extern "C" void kernel_launch(void* const* d_in, const int* in_sizes, int n_in,
                              void* d_out, int out_size) {
    const float* X    = (const float*)d_in[0];
    const float* mask = (const float*)d_in[1];
    const float* adj  = (const float*)d_in[2];
    const float* attr = (const float*)d_in[3];
    const float* rep  = (const float*)d_in[4];
    const float* Wq = (const float*)d_in[5];  const float* bq = (const float*)d_in[6];
    const float* Wk = (const float*)d_in[7];  const float* bk = (const float*)d_in[8];
    const float* Wv = (const float*)d_in[9];  const float* bv = (const float*)d_in[10];
    const float* Wo = (const float*)d_in[11]; const float* bo = (const float*)d_in[12];
    const float* Wf1 = (const float*)d_in[13]; const float* bf1 = (const float*)d_in[14];
    const float* Wf2 = (const float*)d_in[15]; const float* bf2 = (const float*)d_in[16];
    const float* g1 = (const float*)d_in[17]; const float* b1 = (const float*)d_in[18];
    const float* g2 = (const float*)d_in[19]; const float* b2 = (const float*)d_in[20];

    float* out = (float*)d_out;
    float* attn_out = out + (size_t)BN * Dk;

    cudaFuncSetAttribute(attn_kernel, cudaFuncAttributeMaxDynamicSharedMemorySize,
                         ATTN_SMEM_BYTES);
    cudaFuncSetAttribute(gemm_ln, cudaFuncAttributeMaxDynamicSharedMemorySize,
                         LN_SMEM_BYTES);

    float* gq; cudaGetSymbolAddress((void**)&gq, g_Q);
    float* gk; cudaGetSymbolAddress((void**)&gk, g_K);
    float* gv; cudaGetSymbolAddress((void**)&gv, g_V);
    float* gy; cudaGetSymbolAddress((void**)&gy, g_Y);
    float* gx1; cudaGetSymbolAddress((void**)&gx1, g_X1);
    float* ghb; cudaGetSymbolAddress((void**)&ghb, g_Hb);

    QKVArgs qa;
    qa.W[0] = Wq; qa.W[1] = Wk; qa.W[2] = Wv;
    qa.b[0] = bq; qa.b[1] = bk; qa.b[2] = bv;
    qa.O[0] = gq; qa.O[1] = gk; qa.O[2] = gv;
    QKVArgs qz = {};

    gemm_plain<1><<<dim3(64, 4, 3), 256>>>(X, nullptr, nullptr, nullptr, 256, 256, qa);
    bias_kernel<<<8192, 256>>>((const float4*)adj, (const float4*)attr, (const float4*)rep);

    attn_kernel<<<dim3(16, Hk, Bk), 256, ATTN_SMEM_BYTES>>>(mask, attn_out);

    gemm_ln<<<128, 256, LN_SMEM_BYTES>>>(gy, Wo, bo, X, g1, b1, gx1, 256);
    gemm_plain<0><<<dim3(64, 16, 1), 256>>>(gx1, Wf1, bf1, ghb, 256, 1024, qz);
    gemm_ln<<<128, 256, LN_SMEM_BYTES>>>(ghb, Wf2, bf2, gx1, g2, b2, out, 1024);
}

// round 9
// speedup vs baseline: 2.8387x; 1.1017x over previous
#include <cuda_runtime.h>
#include <math.h>
#include <stdint.h>

#define Bk   8
#define Nk   1024
#define Dk   256
#define Hk   8
#define DHk  32
#define DFFk 1024
#define BN   (Bk*Nk)   // 8192

// ---------------- scratch ----------------
__device__ float g_Q [Bk*Hk*Nk*DHk];
__device__ float g_K [Bk*Hk*Nk*DHk];
__device__ float g_V [Bk*Hk*Nk*DHk];
__device__ float g_Y [BN*Dk];          // attn out, tf32-rounded
__device__ float g_X1[BN*Dk];          // fp32 (residual for ffn2)
__device__ float g_X1r[BN*Dk];         // tf32-rounded copy (A for ffn1)
__device__ float g_Hb[(size_t)BN*DFFk];// tf32-rounded relu out
__device__ float g_RB[(size_t)Bk*Nk*Nk];
__device__ float g_Xr[BN*Dk];          // tf32-rounded input X
__device__ float g_Wbuf[786432];       // rounded weights: Wq0 Wk65536 Wv131072 Wo196608 Wf1 262144 Wf2 524288

// ---------------- helpers ----------------
__device__ __forceinline__ float tfr(float x) {
    unsigned u; asm("cvt.rna.tf32.f32 %0, %1;" : "=r"(u) : "f"(x));
    return __uint_as_float(u);
}
__device__ __forceinline__ unsigned FB(float x) { return __float_as_uint(x); }

__device__ __forceinline__ void mma8(float* d, const unsigned* a, unsigned b0, unsigned b1) {
    asm volatile("mma.sync.aligned.m16n8k8.row.col.f32.tf32.tf32.f32 "
        "{%0,%1,%2,%3},{%4,%5,%6,%7},{%8,%9},{%0,%1,%2,%3};"
        : "+f"(d[0]), "+f"(d[1]), "+f"(d[2]), "+f"(d[3])
        : "r"(a[0]), "r"(a[1]), "r"(a[2]), "r"(a[3]), "r"(b0), "r"(b1));
}

__device__ __forceinline__ void cpa16(void* s, const void* g) {
    uint32_t sa = (uint32_t)__cvta_generic_to_shared(s);
    asm volatile("cp.async.cg.shared.global [%0], [%1], 16;" :: "r"(sa), "l"(g));
}
__device__ __forceinline__ void cpa_commit() { asm volatile("cp.async.commit_group;"); }
template<int N> __device__ __forceinline__ void cpa_wait() {
    asm volatile("cp.async.wait_group %0;" :: "n"(N));
}

// load a 128x32 float chunk into smem with pad-36 rows (cp.async)
__device__ __forceinline__ void load_chunk(float* buf, const float* src, int t) {
#pragma unroll
    for (int i = 0; i < 4; i++) {
        int q = t + i * 256;
        int row = q >> 3, c4 = q & 7;
        cpa16(buf + row * 36 + c4 * 4, src + q * 4);
    }
}

// ---------------- prep: tf32-round X and weights ----------------
struct Seg { const float4* s; float4* d; unsigned n; };
struct PrepArgs { Seg seg[7]; };

__global__ void prep_kernel(PrepArgs pa) {
    unsigned i = blockIdx.x * 256 + threadIdx.x;
#pragma unroll
    for (int k = 0; k < 7; k++) {
        if (i < pa.seg[k].n) {
            float4 v = pa.seg[k].s[i];
            v.x = tfr(v.x); v.y = tfr(v.y); v.z = tfr(v.z); v.w = tfr(v.w);
            pa.seg[k].d[i] = v;
            return;
        }
        i -= pa.seg[k].n;
    }
}

// ---------------- kernel: rel_bias = adj + attr + rep ----------------
__global__ void bias_kernel(const float4* __restrict__ a, const float4* __restrict__ b,
                            const float4* __restrict__ c) {
    int i = blockIdx.x * blockDim.x + threadIdx.x;
    float4 x = a[i], y = b[i], z = c[i];
    float4 o;
    o.x = x.x + y.x + z.x; o.y = x.y + y.y + z.y;
    o.z = x.z + y.z + z.z; o.w = x.w + y.w + z.w;
    ((float4*)g_RB)[i] = o;
}

// =====================================================================
// gemm_plain (double-buffered cp.async, pre-rounded inputs):
// MODE 0 = tf32-rounded relu+bias write (ffn1); MODE 1 = fused QKV
// =====================================================================
struct QKVArgs { const float* W[3]; const float* b[3]; float* O[3]; };

#define GP_SMEM_FLOATS (2*4608 + 2*2304)
#define GP_SMEM_BYTES  (GP_SMEM_FLOATS * 4)

template<int MODE>
__global__ __launch_bounds__(256, 2)
void gemm_plain(const float* __restrict__ A, const float* __restrict__ Bw_,
                const float* __restrict__ bias_, float* __restrict__ Out_,
                int K, int NTOT, QKVArgs qa) {
    extern __shared__ float smp[];
    float* Asb = smp;               // 2 x 4608  (128x36)
    float* Bsb = smp + 2 * 4608;    // 2 x 2304  (32x72)
    const int t = threadIdx.x, l = t & 31, wid = t >> 5;
    const int wm = wid & 3, wn = wid >> 2;
    const int mbase = blockIdx.x * 128, nbase = blockIdx.y * 64;

    const float* Bw  = (MODE == 1) ? qa.W[blockIdx.z] : Bw_;
    const float* bias= (MODE == 1) ? qa.b[blockIdx.z] : bias_;
    float* Out       = (MODE == 1) ? qa.O[blockIdx.z] : Out_;

    float acc[2][4][4];
#pragma unroll
    for (int mt = 0; mt < 2; mt++)
#pragma unroll
        for (int nt = 0; nt < 4; nt++)
#pragma unroll
            for (int i = 0; i < 4; i++) acc[mt][nt][i] = 0.f;

    const int nc = K / 32;
    // stage loader
    auto stage = [&](int kc, int bi) {
        float* a = Asb + bi * 4608;
        float* b = Bsb + bi * 2304;
#pragma unroll
        for (int i = 0; i < 4; i++) {
            int idx = t + i * 256;
            int r = idx >> 3, q = idx & 7;
            cpa16(a + r * 36 + q * 4, A + (size_t)(mbase + r) * K + kc + q * 4);
        }
#pragma unroll
        for (int i = 0; i < 2; i++) {
            int idx = t + i * 256;
            int k = idx >> 4, q = idx & 15;
            cpa16(b + k * 72 + q * 4, Bw + (size_t)(kc + k) * NTOT + nbase + q * 4);
        }
    };

    stage(0, 0); cpa_commit();
    for (int c = 0; c < nc; c++) {
        if (c + 1 < nc) { stage((c + 1) * 32, (c + 1) & 1); cpa_commit(); cpa_wait<1>(); }
        else            cpa_wait<0>();
        __syncthreads();
        const float* As = Asb + (c & 1) * 4608;
        const float* Bs = Bsb + (c & 1) * 2304;
#pragma unroll
        for (int ks = 0; ks < 4; ks++) {
            unsigned a[2][4];
#pragma unroll
            for (int mt = 0; mt < 2; mt++) {
                const float* p = &As[(wm * 32 + mt * 16 + (l >> 2)) * 36 + ks * 8 + (l & 3)];
                a[mt][0] = FB(p[0]); a[mt][1] = FB(p[8 * 36]);
                a[mt][2] = FB(p[4]); a[mt][3] = FB(p[8 * 36 + 4]);
            }
#pragma unroll
            for (int nt = 0; nt < 4; nt++) {
                const float* p = &Bs[(ks * 8 + (l & 3)) * 72 + wn * 32 + nt * 8 + (l >> 2)];
                unsigned b0 = FB(p[0]), b1 = FB(p[4 * 72]);
                mma8(acc[0][nt], a[0], b0, b1);
                mma8(acc[1][nt], a[1], b0, b1);
            }
        }
        __syncthreads();
    }

#pragma unroll
    for (int mt = 0; mt < 2; mt++)
#pragma unroll
        for (int nt = 0; nt < 4; nt++) {
            int gcol = nbase + wn * 32 + nt * 8 + (l & 3) * 2;
            float bb0 = bias[gcol], bb1 = bias[gcol + 1];
#pragma unroll
            for (int half = 0; half < 2; half++) {
                int grow = mbase + wm * 32 + mt * 16 + (l >> 2) + half * 8;
                float v0 = acc[mt][nt][half * 2 + 0] + bb0;
                float v1 = acc[mt][nt][half * 2 + 1] + bb1;
                if (MODE == 0) {
                    *(float2*)(Out + (size_t)grow * NTOT + gcol) =
                        make_float2(tfr(fmaxf(v0, 0.f)), tfr(fmaxf(v1, 0.f)));
                } else {
                    int h = gcol >> 5, dd = gcol & 31;
                    int bb = grow >> 10, nn = grow & 1023;
                    float* p = Out + ((size_t)((bb * Hk + h) * Nk + nn)) * DHk + dd;
                    *(float2*)p = make_float2(tfr(v0), tfr(v1));
                }
            }
        }
}

// =====================================================================
// gemm_ln (double-buffered cp.async, pre-rounded inputs):
// Out = LN(A@B + bias + R);  optional OutR = tf32-rounded copy.
// =====================================================================
#define LN_SMEM_FLOATS (2*2304 + 2*8448)    // 21504 (res 16512 overlays)
#define LN_SMEM_BYTES  (LN_SMEM_FLOATS * 4)

__global__ void gemm_ln(const float* __restrict__ A, const float* __restrict__ Bw,
                        const float* __restrict__ bias, const float* __restrict__ R,
                        const float* __restrict__ gam, const float* __restrict__ bet,
                        float* __restrict__ Out, float* __restrict__ OutR, int K) {
    extern __shared__ float sm[];
    float* Asb = sm;                 // 2 x 2304 (64x36)
    float* Bsb = sm + 2 * 2304;      // 2 x 8448 (32x264)
    const int t = threadIdx.x, l = t & 31, wid = t >> 5;
    const int wm = wid & 1, wn = wid >> 1;
    const int mbase = blockIdx.x * 64;

    float acc[2][8][4];
#pragma unroll
    for (int mt = 0; mt < 2; mt++)
#pragma unroll
        for (int nt = 0; nt < 8; nt++)
#pragma unroll
            for (int i = 0; i < 4; i++) acc[mt][nt][i] = 0.f;

    const int nc = K / 32;
    auto stage = [&](int kc, int bi) {
        float* a = Asb + bi * 2304;
        float* b = Bsb + bi * 8448;
#pragma unroll
        for (int i = 0; i < 2; i++) {
            int idx = t + i * 256;
            int r = idx >> 3, q = idx & 7;
            cpa16(a + r * 36 + q * 4, A + (size_t)(mbase + r) * K + kc + q * 4);
        }
#pragma unroll
        for (int i = 0; i < 8; i++) {
            int idx = t + i * 256;
            int k = idx >> 6, q = idx & 63;
            cpa16(b + k * 264 + q * 4, Bw + (size_t)(kc + k) * 256 + q * 4);
        }
    };

    stage(0, 0); cpa_commit();
    for (int c = 0; c < nc; c++) {
        if (c + 1 < nc) { stage((c + 1) * 32, (c + 1) & 1); cpa_commit(); cpa_wait<1>(); }
        else            cpa_wait<0>();
        __syncthreads();
        const float* As = Asb + (c & 1) * 2304;
        const float* Bs = Bsb + (c & 1) * 8448;
#pragma unroll
        for (int ks = 0; ks < 4; ks++) {
            unsigned a[2][4];
#pragma unroll
            for (int mt = 0; mt < 2; mt++) {
                const float* p = &As[(wm * 32 + mt * 16 + (l >> 2)) * 36 + ks * 8 + (l & 3)];
                a[mt][0] = FB(p[0]); a[mt][1] = FB(p[8 * 36]);
                a[mt][2] = FB(p[4]); a[mt][3] = FB(p[8 * 36 + 4]);
            }
#pragma unroll
            for (int nt = 0; nt < 8; nt++) {
                const float* p = &Bs[(ks * 8 + (l & 3)) * 264 + wn * 64 + nt * 8 + (l >> 2)];
                unsigned b0 = FB(p[0]), b1 = FB(p[4 * 264]);
                mma8(acc[0][nt], a[0], b0, b1);
                mma8(acc[1][nt], a[1], b0, b1);
            }
        }
        __syncthreads();
    }

    // ---- epilogue: dump acc to res (overlays buffers), residual + LN ----
    float* res = sm;  // stride 258, 64 rows
#pragma unroll
    for (int mt = 0; mt < 2; mt++)
#pragma unroll
        for (int nt = 0; nt < 8; nt++) {
            int m = wm * 32 + mt * 16 + (l >> 2);
            int n = wn * 64 + nt * 8 + (l & 3) * 2;
            *(float2*)&res[m * 258 + n] = make_float2(acc[mt][nt][0], acc[mt][nt][1]);
            *(float2*)&res[(m + 8) * 258 + n] = make_float2(acc[mt][nt][2], acc[mt][nt][3]);
        }
    __syncthreads();

#pragma unroll
    for (int i = 0; i < 8; i++) {
        int r = wid * 8 + i;
        int grow = mbase + r;
        float s = 0.f;
        for (int c = l; c < 256; c += 32) {
            float v = res[r * 258 + c] + R[(size_t)grow * 256 + c] + bias[c];
            res[r * 258 + c] = v;
            s += v;
        }
#pragma unroll
        for (int o = 16; o > 0; o >>= 1) s += __shfl_xor_sync(0xffffffffu, s, o);
        float mu = s * (1.f / 256.f);
        float s2 = 0.f;
        for (int c = l; c < 256; c += 32) { float dv = res[r * 258 + c] - mu; s2 += dv * dv; }
#pragma unroll
        for (int o = 16; o > 0; o >>= 1) s2 += __shfl_xor_sync(0xffffffffu, s2, o);
        float rs = rsqrtf(s2 * (1.f / 256.f) + 1e-5f);
        for (int c = l; c < 256; c += 32) {
            float ov = (res[r * 258 + c] - mu) * rs * gam[c] + bet[c];
            Out[(size_t)grow * 256 + c] = ov;
            if (OutR) OutR[(size_t)grow * 256 + c] = tfr(ov);
        }
    }
}

// =====================================================================
// Fused attention — unchanged from R8 except g_Y written tf32-rounded.
// =====================================================================
#define ATTN_SMEM_FLOATS (2304 + 4*4608 + 512)
#define ATTN_SMEM_BYTES  (ATTN_SMEM_FLOATS * 4)
#define ZSTRIDE 34
#define ZSLOT   (64 * ZSTRIDE)   // 2176

__global__ __launch_bounds__(256, 2)
void attn_kernel(const float* __restrict__ mask, float* __restrict__ attn_out) {
    extern __shared__ float sm[];
    float* Qs = sm;
    float* Kb[4] = { sm + 2304, sm + 2304 + 4608, sm + 2304 + 2*4608, sm + 2304 + 3*4608 };
    float* st = sm + 2304 + 4*4608;

    const int t = threadIdx.x, l = t & 31, wid = t >> 5;
    const int wm = wid & 1, wn = wid >> 1;
    const int m0 = blockIdx.x * 64, h = blockIdx.y, b = blockIdx.z;

    const float* Qg  = g_Q + ((size_t)((b * Hk + h) * Nk + m0)) * DHk;
    const float* Kg  = g_K + ((size_t)((b * Hk + h) * Nk)) * DHk;
    const float* Vg  = g_V + ((size_t)((b * Hk + h) * Nk)) * DHk;
    const float* RBg = g_RB + ((size_t)(b * Nk + m0)) * Nk;
    const float* mkp = mask + b * Nk;
    const float scale = 0.17677669529663687f;

#pragma unroll
    for (int i = 0; i < 2; i++) {
        int q = t + i * 256;
        cpa16(Qs + (q >> 3) * 36 + (q & 7) * 4, Qg + q * 4);
    }
    load_chunk(Kb[0], Kg, t); cpa_commit();
    load_chunk(Kb[1], Kg + 4096, t); cpa_commit();
    load_chunk(Kb[2], Kg + 2 * 4096, t); cpa_commit();

    float mL[4], lL[4];
#pragma unroll
    for (int r = 0; r < 4; r++) { mL[r] = -1e30f; lL[r] = 0.f; }

    // ---- PASS 1 (tiered waits; see R8 ledger comment) ----
    for (int c = 0; c < 8; c++) {
        if (c < 6)       cpa_wait<2>();
        else if (c == 6) cpa_wait<1>();
        else             cpa_wait<0>();
        __syncthreads();
        if (c < 5) { load_chunk(Kb[(c + 3) & 3], Kg + (size_t)(c + 3) * 4096, t); cpa_commit(); }

        float* kb = Kb[c & 3];
        float acc[2][4][4];
#pragma unroll
        for (int mt = 0; mt < 2; mt++)
#pragma unroll
            for (int nt = 0; nt < 4; nt++)
#pragma unroll
                for (int i = 0; i < 4; i++) acc[mt][nt][i] = 0.f;

#pragma unroll
        for (int ks = 0; ks < 4; ks++) {
            unsigned aq[2][4];
#pragma unroll
            for (int mt = 0; mt < 2; mt++) {
                const float* p = &Qs[(wm * 32 + mt * 16 + (l >> 2)) * 36 + ks * 8 + (l & 3)];
                aq[mt][0] = FB(p[0]); aq[mt][1] = FB(p[8 * 36]);
                aq[mt][2] = FB(p[4]); aq[mt][3] = FB(p[8 * 36 + 4]);
            }
#pragma unroll
            for (int nt = 0; nt < 4; nt++) {
                const float* p = &kb[(wn * 32 + nt * 8 + (l >> 2)) * 36 + ks * 8 + (l & 3)];
                unsigned b0 = FB(p[0]), b1 = FB(p[4]);
                mma8(acc[0][nt], aq[0], b0, b1);
                mma8(acc[1][nt], aq[1], b0, b1);
            }
        }

        float2 mk2[4];
#pragma unroll
        for (int nt = 0; nt < 4; nt++)
            mk2[nt] = *(const float2*)(mkp + c * 128 + wn * 32 + nt * 8 + (l & 3) * 2);

#pragma unroll
        for (int r = 0; r < 4; r++) {
            int row = wm * 32 + (r >> 1) * 16 + (r & 1) * 8 + (l >> 2);
            const float* rbrow = RBg + (size_t)row * Nk + c * 128 + wn * 32;
            float vs[8], vmax = -1e30f;
#pragma unroll
            for (int nt = 0; nt < 4; nt++) {
                float2 rb2 = *(const float2*)(rbrow + nt * 8 + (l & 3) * 2);
                int ai = (r & 1) * 2;
                float s0 = acc[r >> 1][nt][ai] * scale + rb2.x;
                float s1 = acc[r >> 1][nt][ai + 1] * scale + rb2.y;
                if (!(mk2[nt].x > 0.f)) s0 = -1e9f;
                if (!(mk2[nt].y > 0.f)) s1 = -1e9f;
                vs[nt * 2] = s0; vs[nt * 2 + 1] = s1;
                vmax = fmaxf(vmax, fmaxf(s0, s1));
            }
            float mn = fmaxf(mL[r], vmax);
            float lsum = lL[r] * __expf(mL[r] - mn);
#pragma unroll
            for (int k = 0; k < 8; k++) lsum += __expf(vs[k] - mn);
            mL[r] = mn; lL[r] = lsum;
        }
    }

    // ---- merge stats ----
#pragma unroll
    for (int r = 0; r < 4; r++) {
        float m = mL[r], lv = lL[r];
#pragma unroll
        for (int o = 1; o <= 2; o <<= 1) {
            float m2 = __shfl_xor_sync(0xffffffffu, m, o);
            float l2 = __shfl_xor_sync(0xffffffffu, lv, o);
            float mn = fmaxf(m, m2);
            lv = lv * __expf(m - mn) + l2 * __expf(m2 - mn);
            m = mn;
        }
        if ((l & 3) == 0) {
            int row = wm * 32 + (r >> 1) * 16 + (r & 1) * 8 + (l >> 2);
            st[(row * 4 + wn) * 2]     = m;
            st[(row * 4 + wn) * 2 + 1] = lv;
        }
    }
    __syncthreads();
    float mF[4], ilF[4];
#pragma unroll
    for (int r = 0; r < 4; r++) {
        int row = wm * 32 + (r >> 1) * 16 + (r & 1) * 8 + (l >> 2);
        float m = -1e30f, lv = 0.f;
#pragma unroll
        for (int w2 = 0; w2 < 4; w2++) {
            float m2 = st[(row * 4 + w2) * 2];
            float l2 = st[(row * 4 + w2) * 2 + 1];
            float mn = fmaxf(m, m2);
            lv = lv * __expf(m - mn) + l2 * __expf(m2 - mn);
            m = mn;
        }
        mF[r] = m; ilF[r] = 1.f / lv;
    }
    __syncthreads();

    // ---- pass 2 prologue ----
    load_chunk(Kb[0], Kg, t);
    load_chunk(Kb[1], Vg, t);
    cpa_commit();

    float Yacc[2][4][4];
#pragma unroll
    for (int mt = 0; mt < 2; mt++)
#pragma unroll
        for (int g = 0; g < 4; g++)
#pragma unroll
            for (int i = 0; i < 4; i++) Yacc[mt][g][i] = 0.f;

    const int rlane = l & 3;
    const int lbase = l & ~3;
    const int slo = lbase | (rlane >> 1);
    const int shi = lbase | ((rlane >> 1) + 2);
    const bool odd = (rlane & 1) != 0;

    // ---- PASS 2 ----
    for (int c = 0; c < 8; c++) {
        cpa_wait<0>();
        __syncthreads();
        if (c < 7) {
            load_chunk(Kb[2 * ((c + 1) & 1)],     Kg + (size_t)(c + 1) * 4096, t);
            load_chunk(Kb[2 * ((c + 1) & 1) + 1], Vg + (size_t)(c + 1) * 4096, t);
            cpa_commit();
        }
        float* kb = Kb[2 * (c & 1)];
        float* vb = Kb[2 * (c & 1) + 1];

        float acc[2][4][4];
#pragma unroll
        for (int mt = 0; mt < 2; mt++)
#pragma unroll
            for (int nt = 0; nt < 4; nt++)
#pragma unroll
                for (int i = 0; i < 4; i++) acc[mt][nt][i] = 0.f;

#pragma unroll
        for (int ks = 0; ks < 4; ks++) {
            unsigned aq[2][4];
#pragma unroll
            for (int mt = 0; mt < 2; mt++) {
                const float* p = &Qs[(wm * 32 + mt * 16 + (l >> 2)) * 36 + ks * 8 + (l & 3)];
                aq[mt][0] = FB(p[0]); aq[mt][1] = FB(p[8 * 36]);
                aq[mt][2] = FB(p[4]); aq[mt][3] = FB(p[8 * 36 + 4]);
            }
#pragma unroll
            for (int nt = 0; nt < 4; nt++) {
                const float* p = &kb[(wn * 32 + nt * 8 + (l >> 2)) * 36 + ks * 8 + (l & 3)];
                unsigned b0 = FB(p[0]), b1 = FB(p[4]);
                mma8(acc[0][nt], aq[0], b0, b1);
                mma8(acc[1][nt], aq[1], b0, b1);
            }
        }

        float2 mk2[4];
#pragma unroll
        for (int nt = 0; nt < 4; nt++)
            mk2[nt] = *(const float2*)(mkp + c * 128 + wn * 32 + nt * 8 + (l & 3) * 2);

#pragma unroll
        for (int r = 0; r < 4; r++) {
            int row = wm * 32 + (r >> 1) * 16 + (r & 1) * 8 + (l >> 2);
            const float* rbrow = RBg + (size_t)row * Nk + c * 128 + wn * 32;
            float* arow = attn_out + (((size_t)((b * Hk + h) * Nk + m0 + row)) * Nk)
                          + c * 128 + wn * 32;
#pragma unroll
            for (int nt = 0; nt < 4; nt++) {
                float2 rb2 = *(const float2*)(rbrow + nt * 8 + (l & 3) * 2);
                int ai = (r & 1) * 2;
                float s0 = acc[r >> 1][nt][ai] * scale + rb2.x;
                float s1 = acc[r >> 1][nt][ai + 1] * scale + rb2.y;
                if (!(mk2[nt].x > 0.f)) s0 = -1e9f;
                if (!(mk2[nt].y > 0.f)) s1 = -1e9f;
                float p0 = __expf(s0 - mF[r]) * ilF[r];
                float p1 = __expf(s1 - mF[r]) * ilF[r];
                *(float2*)(arow + nt * 8 + (l & 3) * 2) = make_float2(p0, p1);
                acc[r >> 1][nt][ai]     = tfr(p0);
                acc[r >> 1][nt][ai + 1] = tfr(p1);
            }
        }

        // ---- P@V ----
#pragma unroll
        for (int mt = 0; mt < 2; mt++)
#pragma unroll
            for (int nt = 0; nt < 4; nt++) {
                float c0 = acc[mt][nt][0], c1 = acc[mt][nt][1];
                float c2 = acc[mt][nt][2], c3 = acc[mt][nt][3];
                float v00 = __shfl_sync(0xffffffffu, c0, slo);
                float v01 = __shfl_sync(0xffffffffu, c1, slo);
                float v02 = __shfl_sync(0xffffffffu, c2, slo);
                float v03 = __shfl_sync(0xffffffffu, c3, slo);
                float v10 = __shfl_sync(0xffffffffu, c0, shi);
                float v11 = __shfl_sync(0xffffffffu, c1, shi);
                float v12 = __shfl_sync(0xffffffffu, c2, shi);
                float v13 = __shfl_sync(0xffffffffu, c3, shi);
                unsigned afr[4];
                afr[0] = FB(odd ? v01 : v00);
                afr[1] = FB(odd ? v03 : v02);
                afr[2] = FB(odd ? v11 : v10);
                afr[3] = FB(odd ? v13 : v12);
#pragma unroll
                for (int g = 0; g < 4; g++) {
                    const float* pv = &vb[(wn * 32 + nt * 8 + (l & 3)) * 36 + g * 8 + (l >> 2)];
                    unsigned b0 = FB(pv[0]), b1 = FB(pv[4 * 36]);
                    mma8(Yacc[mt][g], afr, b0, b1);
                }
            }
    }

    // ---- final cross-warp Y reduction (tf32-rounded for oproj A) ----
    float* Z = Kb[0];
    __syncthreads();
#pragma unroll
    for (int mt = 0; mt < 2; mt++)
#pragma unroll
        for (int g = 0; g < 4; g++) {
            int row = wm * 32 + mt * 16 + (l >> 2);
            int col = g * 8 + (l & 3) * 2;
            float* zp = Z + wn * ZSLOT + row * ZSTRIDE + col;
            *(float2*)zp = make_float2(Yacc[mt][g][0], Yacc[mt][g][1]);
            *(float2*)(zp + 8 * ZSTRIDE) = make_float2(Yacc[mt][g][2], Yacc[mt][g][3]);
        }
    __syncthreads();

#pragma unroll
    for (int j = 0; j < 4; j++) {
        int e2 = t * 4 + j;
        int row = e2 >> 4, col = (e2 & 15) * 2;
        const float* zp = Z + row * ZSTRIDE + col;
        float2 z0 = *(const float2*)(zp);
        float2 z1 = *(const float2*)(zp + ZSLOT);
        float2 z2 = *(const float2*)(zp + 2 * ZSLOT);
        float2 z3 = *(const float2*)(zp + 3 * ZSLOT);
        float y0 = tfr(z0.x + z1.x + z2.x + z3.x);
        float y1 = tfr(z0.y + z1.y + z2.y + z3.y);
        float* yp = g_Y + ((size_t)(b * Nk + m0 + row)) * Dk + h * DHk + col;
        *(float2*)yp = make_float2(y0, y1);
    }
}

// ---------------- launch ----------------
extern "C" void kernel_launch(void* const* d_in, const int* in_sizes, int n_in,
                              void* d_out, int out_size) {
    const float* X    = (const float*)d_in[0];
    const float* mask = (const float*)d_in[1];
    const float* adj  = (const float*)d_in[2];
    const float* attr = (const float*)d_in[3];
    const float* rep  = (const float*)d_in[4];
    const float* Wq = (const float*)d_in[5];  const float* bq = (const float*)d_in[6];
    const float* Wk = (const float*)d_in[7];  const float* bk = (const float*)d_in[8];
    const float* Wv = (const float*)d_in[9];  const float* bv = (const float*)d_in[10];
    const float* Wo = (const float*)d_in[11]; const float* bo = (const float*)d_in[12];
    const float* Wf1 = (const float*)d_in[13]; const float* bf1 = (const float*)d_in[14];
    const float* Wf2 = (const float*)d_in[15]; const float* bf2 = (const float*)d_in[16];
    const float* g1 = (const float*)d_in[17]; const float* b1 = (const float*)d_in[18];
    const float* g2 = (const float*)d_in[19]; const float* b2 = (const float*)d_in[20];

    float* out = (float*)d_out;
    float* attn_out = out + (size_t)BN * Dk;

    cudaFuncSetAttribute(attn_kernel, cudaFuncAttributeMaxDynamicSharedMemorySize,
                         ATTN_SMEM_BYTES);
    cudaFuncSetAttribute(gemm_ln, cudaFuncAttributeMaxDynamicSharedMemorySize,
                         LN_SMEM_BYTES);
    cudaFuncSetAttribute(gemm_plain<0>, cudaFuncAttributeMaxDynamicSharedMemorySize,
                         GP_SMEM_BYTES);
    cudaFuncSetAttribute(gemm_plain<1>, cudaFuncAttributeMaxDynamicSharedMemorySize,
                         GP_SMEM_BYTES);

    float* gq;  cudaGetSymbolAddress((void**)&gq,  g_Q);
    float* gk;  cudaGetSymbolAddress((void**)&gk,  g_K);
    float* gv;  cudaGetSymbolAddress((void**)&gv,  g_V);
    float* gy;  cudaGetSymbolAddress((void**)&gy,  g_Y);
    float* gx1; cudaGetSymbolAddress((void**)&gx1, g_X1);
    float* gx1r;cudaGetSymbolAddress((void**)&gx1r,g_X1r);
    float* ghb; cudaGetSymbolAddress((void**)&ghb, g_Hb);
    float* gxr; cudaGetSymbolAddress((void**)&gxr, g_Xr);
    float* gw;  cudaGetSymbolAddress((void**)&gw,  g_Wbuf);

    // prep: round X + weights into scratch
    PrepArgs pa;
    pa.seg[0] = { (const float4*)X,   (float4*)gxr,            524288 };
    pa.seg[1] = { (const float4*)Wq,  (float4*)(gw + 0),        16384 };
    pa.seg[2] = { (const float4*)Wk,  (float4*)(gw + 65536),    16384 };
    pa.seg[3] = { (const float4*)Wv,  (float4*)(gw + 131072),   16384 };
    pa.seg[4] = { (const float4*)Wo,  (float4*)(gw + 196608),   16384 };
    pa.seg[5] = { (const float4*)Wf1, (float4*)(gw + 262144),   65536 };
    pa.seg[6] = { (const float4*)Wf2, (float4*)(gw + 524288),   65536 };
    prep_kernel<<<2816, 256>>>(pa);

    bias_kernel<<<8192, 256>>>((const float4*)adj, (const float4*)attr, (const float4*)rep);

    QKVArgs qa;
    qa.W[0] = gw + 0;      qa.W[1] = gw + 65536;  qa.W[2] = gw + 131072;
    qa.b[0] = bq;          qa.b[1] = bk;          qa.b[2] = bv;
    qa.O[0] = gq;          qa.O[1] = gk;          qa.O[2] = gv;
    QKVArgs qz = {};

    gemm_plain<1><<<dim3(64, 4, 3), 256, GP_SMEM_BYTES>>>(gxr, nullptr, nullptr, nullptr,
                                                          256, 256, qa);

    attn_kernel<<<dim3(16, Hk, Bk), 256, ATTN_SMEM_BYTES>>>(mask, attn_out);

    gemm_ln<<<128, 256, LN_SMEM_BYTES>>>(gy, gw + 196608, bo, X, g1, b1, gx1, gx1r, 256);
    gemm_plain<0><<<dim3(64, 16, 1), 256, GP_SMEM_BYTES>>>(gx1r, gw + 262144, bf1, ghb,
                                                           256, 1024, qz);
    gemm_ln<<<128, 256, LN_SMEM_BYTES>>>(ghb, gw + 524288, bf2, gx1, g2, b2, out, nullptr, 1024);
}